// round 2
// baseline (speedup 1.0000x reference)
#include <cuda_runtime.h>

#define NB 16
#define LA 1024
#define LB 1024
#define HD 512
#define EPSV 1e-13f

// Scratch: sim matrix S and probability matrix P (reused for both directions).
__device__ float g_S[(long long)NB * LA * LB];
__device__ float g_P[(long long)NB * LA * LB];

// ---------------------------------------------------------------------------
// SGEMM, 128x128 block tile, BK=8, 256 threads, 8x8 per-thread micro-tile,
// double-buffered shared memory (one __syncthreads per k-tile).
// MODE 0: NT  C[m,n] = sum_k A[m,k] * B[n,k]      (A:[M,K] rm, B:[N,K] rm)
// MODE 1: NN  C[m,n] = sum_k A[m,k] * B[k,n]      (A:[M,K] rm, B:[K,N] rm)
// MODE 2: TN  C[m,n] = sum_k A[k,m] * B[k,n]      (A:[K,M] rm, B:[K,N] rm)
// All dims must be multiples of the tile sizes (true here).
// ---------------------------------------------------------------------------
template <int MODE>
__global__ __launch_bounds__(256, 2)
void sgemm_kernel(const float* __restrict__ gA, const float* __restrict__ gB,
                  float* __restrict__ gC,
                  int K, int lda, int ldb, int ldc,
                  long long sA, long long sB, long long sC)
{
    __shared__ float As[2][8][128];
    __shared__ float Bs[2][8][128];

    const float* A = gA + (long long)blockIdx.z * sA;
    const float* Bm = gB + (long long)blockIdx.z * sB;
    float* C = gC + (long long)blockIdx.z * sC;

    const int m0 = blockIdx.y * 128;
    const int n0 = blockIdx.x * 128;
    const int tid = threadIdx.x;
    const int tx = tid & 15;          // n-direction (8 cols each)
    const int ty = tid >> 4;          // m-direction (8 rows each)

    // load-index helpers
    const int rm_row = tid >> 1;            // 0..127 (row-major [X,K] tile loads)
    const int rm_k4  = (tid & 1) * 4;       // 0 or 4
    const int kn_r   = tid >> 5;            // 0..7   ([K,X] tile loads)
    const int kn_c   = (tid & 31) * 4;      // 0..124

    float4 aReg, bReg;
    float acc[8][8];
#pragma unroll
    for (int i = 0; i < 8; i++)
#pragma unroll
        for (int j = 0; j < 8; j++) acc[i][j] = 0.f;

    const int nkt = K >> 3;

    // ---- tile 0 load ----
    {
        if (MODE == 2)
            aReg = *(const float4*)&A[(long long)kn_r * lda + m0 + kn_c];
        else
            aReg = *(const float4*)&A[(long long)(m0 + rm_row) * lda + rm_k4];
        if (MODE == 0)
            bReg = *(const float4*)&Bm[(long long)(n0 + rm_row) * ldb + rm_k4];
        else
            bReg = *(const float4*)&Bm[(long long)kn_r * ldb + n0 + kn_c];

        if (MODE == 2) {
            *(float4*)&As[0][kn_r][kn_c] = aReg;
        } else {
            As[0][rm_k4 + 0][rm_row] = aReg.x;
            As[0][rm_k4 + 1][rm_row] = aReg.y;
            As[0][rm_k4 + 2][rm_row] = aReg.z;
            As[0][rm_k4 + 3][rm_row] = aReg.w;
        }
        if (MODE == 0) {
            Bs[0][rm_k4 + 0][rm_row] = bReg.x;
            Bs[0][rm_k4 + 1][rm_row] = bReg.y;
            Bs[0][rm_k4 + 2][rm_row] = bReg.z;
            Bs[0][rm_k4 + 3][rm_row] = bReg.w;
        } else {
            *(float4*)&Bs[0][kn_r][kn_c] = bReg;
        }
    }
    __syncthreads();

    int buf = 0;
    for (int kt = 0; kt < nkt; kt++) {
        if (kt + 1 < nkt) {
            const int k0 = (kt + 1) * 8;
            if (MODE == 2)
                aReg = *(const float4*)&A[(long long)(k0 + kn_r) * lda + m0 + kn_c];
            else
                aReg = *(const float4*)&A[(long long)(m0 + rm_row) * lda + k0 + rm_k4];
            if (MODE == 0)
                bReg = *(const float4*)&Bm[(long long)(n0 + rm_row) * ldb + k0 + rm_k4];
            else
                bReg = *(const float4*)&Bm[(long long)(k0 + kn_r) * ldb + n0 + kn_c];
        }

#pragma unroll
        for (int kk = 0; kk < 8; kk++) {
            float a[8], b[8];
            *(float4*)&a[0] = *(const float4*)&As[buf][kk][ty * 8];
            *(float4*)&a[4] = *(const float4*)&As[buf][kk][ty * 8 + 4];
            *(float4*)&b[0] = *(const float4*)&Bs[buf][kk][tx * 8];
            *(float4*)&b[4] = *(const float4*)&Bs[buf][kk][tx * 8 + 4];
#pragma unroll
            for (int i = 0; i < 8; i++)
#pragma unroll
                for (int j = 0; j < 8; j++)
                    acc[i][j] = fmaf(a[i], b[j], acc[i][j]);
        }

        if (kt + 1 < nkt) {
            const int nb = buf ^ 1;
            if (MODE == 2) {
                *(float4*)&As[nb][kn_r][kn_c] = aReg;
            } else {
                As[nb][rm_k4 + 0][rm_row] = aReg.x;
                As[nb][rm_k4 + 1][rm_row] = aReg.y;
                As[nb][rm_k4 + 2][rm_row] = aReg.z;
                As[nb][rm_k4 + 3][rm_row] = aReg.w;
            }
            if (MODE == 0) {
                Bs[nb][rm_k4 + 0][rm_row] = bReg.x;
                Bs[nb][rm_k4 + 1][rm_row] = bReg.y;
                Bs[nb][rm_k4 + 2][rm_row] = bReg.z;
                Bs[nb][rm_k4 + 3][rm_row] = bReg.w;
            } else {
                *(float4*)&Bs[nb][kn_r][kn_c] = bReg;
            }
            __syncthreads();
            buf = nb;
        }
    }

#pragma unroll
    for (int i = 0; i < 8; i++) {
        long long off = (long long)(m0 + ty * 8 + i) * ldc + n0 + tx * 8;
        *(float4*)&C[off]     = make_float4(acc[i][0], acc[i][1], acc[i][2], acc[i][3]);
        *(float4*)&C[off + 4] = make_float4(acc[i][4], acc[i][5], acc[i][6], acc[i][7]);
    }
}

// ---------------------------------------------------------------------------
// Row-direction masked softmax: P[b,i,j] = pmask[i] * hm[j]*e(l_j - m) / (E + eps*D)
// where l_j = S[b,i,j]*hm[j]; m = max_j l_j; D = sum_all e; E = sum_{hm=1} e.
// One block (256 thr) per (i, b) row; each thread owns 4 contiguous j.
// ---------------------------------------------------------------------------
__global__ __launch_bounds__(256)
void row_softmax_kernel(const float* __restrict__ S, float* __restrict__ P,
                        const float* __restrict__ pmask, const float* __restrict__ hmask)
{
    const int i = blockIdx.x;
    const int b = blockIdx.y;
    const long long rowoff = ((long long)b * LA + i) * LB;
    const int tid = threadIdx.x;

    float4 s = *(const float4*)&S[rowoff + tid * 4];
    float4 h = *(const float4*)&hmask[(long long)b * LB + tid * 4];
    float l0 = s.x * h.x, l1 = s.y * h.y, l2 = s.z * h.z, l3 = s.w * h.w;

    __shared__ float redA[8], redB[8];

    // block max
    float v = fmaxf(fmaxf(l0, l1), fmaxf(l2, l3));
#pragma unroll
    for (int o = 16; o; o >>= 1) v = fmaxf(v, __shfl_xor_sync(0xffffffffu, v, o));
    if ((tid & 31) == 0) redA[tid >> 5] = v;
    __syncthreads();
    float m = redA[0];
#pragma unroll
    for (int w = 1; w < 8; w++) m = fmaxf(m, redA[w]);
    __syncthreads();

    float e0 = __expf(l0 - m), e1 = __expf(l1 - m), e2 = __expf(l2 - m), e3 = __expf(l3 - m);
    float d = e0 + e1 + e2 + e3;
    float e = h.x * e0 + h.y * e1 + h.z * e2 + h.w * e3;
#pragma unroll
    for (int o = 16; o; o >>= 1) {
        d += __shfl_xor_sync(0xffffffffu, d, o);
        e += __shfl_xor_sync(0xffffffffu, e, o);
    }
    if ((tid & 31) == 0) { redA[tid >> 5] = d; redB[tid >> 5] = e; }
    __syncthreads();
    float D = 0.f, E = 0.f;
#pragma unroll
    for (int w = 0; w < 8; w++) { D += redA[w]; E += redB[w]; }

    const float pm = pmask[(long long)b * LA + i];
    const float scale = pm / (E + EPSV * D);

    float4 o4 = make_float4(h.x * e0 * scale, h.y * e1 * scale,
                            h.z * e2 * scale, h.w * e3 * scale);
    *(float4*)&P[rowoff + tid * 4] = o4;
}

// ---------------------------------------------------------------------------
// Column-direction masked softmax over i (LA) for each column j (LB):
// P[b,i,j] = pm[i]*e(l_i - m_j) * hmask[j] / (E_j + eps*D_j),  l_i = S[b,i,j]*pm[i].
// Block = 32 columns x 8 row-strides (256 thr). Grid (LB/32, NB).
// ---------------------------------------------------------------------------
__global__ __launch_bounds__(256)
void col_softmax_kernel(const float* __restrict__ S, float* __restrict__ P,
                        const float* __restrict__ pmask, const float* __restrict__ hmask)
{
    const int b = blockIdx.y;
    const int tx = threadIdx.x & 31;
    const int ty = threadIdx.x >> 5;
    const int j = blockIdx.x * 32 + tx;
    const float* Sb = S + (long long)b * LA * LB;
    float* Pb = P + (long long)b * LA * LB;
    const float* pm = pmask + (long long)b * LA;

    __shared__ float red[8][32];

    float mx = -1e30f;
    for (int r = ty; r < LA; r += 8) {
        float l = Sb[(long long)r * LB + j] * pm[r];
        mx = fmaxf(mx, l);
    }
    red[ty][tx] = mx;
    __syncthreads();
    mx = red[0][tx];
#pragma unroll
    for (int t = 1; t < 8; t++) mx = fmaxf(mx, red[t][tx]);
    __syncthreads();

    float D = 0.f, E = 0.f;
    for (int r = ty; r < LA; r += 8) {
        float pmr = pm[r];
        float ev = __expf(Sb[(long long)r * LB + j] * pmr - mx);
        D += ev;
        E += pmr * ev;
    }
    red[ty][tx] = D;
    __syncthreads();
    D = 0.f;
#pragma unroll
    for (int t = 0; t < 8; t++) D += red[t][tx];
    __syncthreads();
    red[ty][tx] = E;
    __syncthreads();
    E = 0.f;
#pragma unroll
    for (int t = 0; t < 8; t++) E += red[t][tx];
    __syncthreads();

    const float scale = hmask[(long long)b * LB + j] / (E + EPSV * D);

    for (int r = ty; r < LA; r += 8) {
        float pmr = pm[r];
        float ev = __expf(Sb[(long long)r * LB + j] * pmr - mx);
        Pb[(long long)r * LB + j] = pmr * ev * scale;
    }
}

// ---------------------------------------------------------------------------
extern "C" void kernel_launch(void* const* d_in, const int* in_sizes, int n_in,
                              void* d_out, int out_size)
{
    const float* prem  = (const float*)d_in[0];  // [16,1024,512]
    const float* pmask = (const float*)d_in[1];  // [16,1024]
    const float* hyp   = (const float*)d_in[2];  // [16,1024,512]
    const float* hmask = (const float*)d_in[3];  // [16,1024]

    float* AP = (float*)d_out;                               // [16,1024,512]
    float* AH = AP + (long long)NB * LA * HD;                // [16,1024,512]

    void* pS; cudaGetSymbolAddress(&pS, g_S);
    void* pP; cudaGetSymbolAddress(&pP, g_P);
    float* S = (float*)pS;
    float* P = (float*)pP;

    const long long sAB = (long long)LA * HD;   // 524288
    const long long sS  = (long long)LA * LB;   // 1048576

    // 1) S = premise @ hypothesis^T  (NT, M=1024, N=1024, K=512)
    {
        dim3 grid(LB / 128, LA / 128, NB);
        sgemm_kernel<0><<<grid, 256>>>(prem, hyp, S, HD, HD, HD, LB, sAB, sAB, sS);
    }
    // 2) row masked-softmax -> P (pmask folded in)
    {
        dim3 grid(LA, NB);
        row_softmax_kernel<<<grid, 256>>>(S, P, pmask, hmask);
    }
    // 3) AP = P @ hypothesis  (NN, M=1024, N=512, K=1024)
    {
        dim3 grid(HD / 128, LA / 128, NB);
        sgemm_kernel<1><<<grid, 256>>>(P, hyp, AP, LB, LB, HD, HD, sS, sAB, sAB);
    }
    // 4) column masked-softmax -> P (hmask folded in)
    {
        dim3 grid(LB / 32, NB);
        col_softmax_kernel<<<grid, 256>>>(S, P, pmask, hmask);
    }
    // 5) AH = P^T @ premise  (TN, M=1024(j), N=512, K=1024(i))
    {
        dim3 grid(HD / 128, LB / 128, NB);
        sgemm_kernel<2><<<grid, 256>>>(P, prem, AH, LA, LB, HD, HD, sS, sAB, sAB);
    }
}

// round 5
// speedup vs baseline: 2.1926x; 2.1926x over previous
#include <cuda_runtime.h>
#include <cuda_bf16.h>
#include <cstdint>

#define NB 16
#define LA 1024
#define LB 1024
#define HD 512
#define EPSV 1e-13f

__device__ float g_S[(long long)NB * LA * LB];
__device__ float g_P[(long long)NB * LA * LB];

// ---------------------------------------------------------------------------
// Common helpers
// ---------------------------------------------------------------------------
__device__ __forceinline__ uint32_t smem_u32(const void* p) {
    uint32_t a;
    asm("{ .reg .u64 t; cvta.to.shared.u64 t, %1; cvt.u32.u64 %0, t; }" : "=r"(a) : "l"(p));
    return a;
}
__device__ __forceinline__ uint32_t swz(uint32_t off) { return off ^ ((off >> 3) & 0x70); }

// fp32 -> (hi,lo) bf16 split pair store into SW128-swizzled smem [128 rows x 128B]
__device__ __forceinline__ void store_pair(uint32_t base_hi, uint32_t base_lo,
                                           int x, int k, float v0, float v1) {
    __nv_bfloat162 h = __floats2bfloat162_rn(v0, v1);
    float r0 = v0 - __bfloat162float(h.x);
    float r1 = v1 - __bfloat162float(h.y);
    __nv_bfloat162 l = __floats2bfloat162_rn(r0, r1);
    uint32_t sw = swz((uint32_t)(x * 128 + 2 * k));
    uint32_t hv = *(uint32_t*)&h;
    uint32_t lv = *(uint32_t*)&l;
    asm volatile("st.shared.b32 [%0], %1;" :: "r"(base_hi + sw), "r"(hv) : "memory");
    asm volatile("st.shared.b32 [%0], %1;" :: "r"(base_lo + sw), "r"(lv) : "memory");
}

// TRANS=false: src[x][k] (k contiguous, pitch ld). TRANS=true: src[k][x].
template <bool TRANS>
__device__ __forceinline__ void load_tile(const float* __restrict__ src, int ld,
                                          int x0, int k0, uint32_t hi, uint32_t lo, int tid) {
    if (!TRANS) {
#pragma unroll
        for (int it = 0; it < 8; it++) {
            int u = it * 256 + tid;
            int x = u >> 4;
            int k = (u & 15) * 4;
            float4 v = *(const float4*)&src[(long long)(x0 + x) * ld + k0 + k];
            store_pair(hi, lo, x, k, v.x, v.y);
            store_pair(hi, lo, x, k + 2, v.z, v.w);
        }
    } else {
#pragma unroll
        for (int it = 0; it < 4; it++) {
            int u = it * 256 + tid;
            int x = (u >> 5) * 4;
            int k = (u & 31) * 2;
            const float* p0 = &src[(long long)(k0 + k) * ld + x0 + x];
            float4 v0 = *(const float4*)p0;
            float4 v1 = *(const float4*)(p0 + ld);
            store_pair(hi, lo, x + 0, k, v0.x, v1.x);
            store_pair(hi, lo, x + 1, k, v0.y, v1.y);
            store_pair(hi, lo, x + 2, k, v0.z, v1.z);
            store_pair(hi, lo, x + 3, k, v0.w, v1.w);
        }
    }
}

#if defined(__CUDA_ARCH_FEAT_SM103_ALL)
// ---------------------------------------------------------------------------
// tcgen05 helpers (only in an arch-specific sm_103a pass)
// ---------------------------------------------------------------------------
__device__ __forceinline__ uint32_t elect1() {
    uint32_t p;
    asm volatile("{ .reg .pred p; elect.sync _|p, 0xFFFFFFFF; selp.b32 %0,1,0,p; }" : "=r"(p));
    return p;
}
__device__ __forceinline__ void mbar_init(uint32_t mbar, uint32_t cnt) {
    asm volatile("mbarrier.init.shared.b64 [%0], %1;" :: "r"(mbar), "r"(cnt) : "memory");
}
__device__ __forceinline__ void mbar_inval(uint32_t mbar) {
    asm volatile("mbarrier.inval.shared.b64 [%0];" :: "r"(mbar) : "memory");
}
__device__ __forceinline__ void mbar_wait(uint32_t mbar, uint32_t parity) {
    asm volatile(
        "{\n\t.reg .pred P;\n\t"
        "WL%=:\n\t"
        "mbarrier.try_wait.parity.acquire.cta.shared::cta.b64 P, [%0], %1, 0x989680;\n\t"
        "@P bra WD%=;\n\t"
        "bra WL%=;\n\t"
        "WD%=:\n\t}"
        :: "r"(mbar), "r"(parity) : "memory");
}
__device__ __forceinline__ void tmem_alloc(uint32_t dst_smem, uint32_t ncols) {
    asm volatile("tcgen05.alloc.cta_group::1.sync.aligned.shared::cta.b32 [%0], %1;"
                 :: "r"(dst_smem), "r"(ncols) : "memory");
}
__device__ __forceinline__ void tmem_relinq() {
    asm volatile("tcgen05.relinquish_alloc_permit.cta_group::1.sync.aligned;");
}
__device__ __forceinline__ void tmem_dealloc(uint32_t tmem, uint32_t ncols) {
    asm volatile("tcgen05.dealloc.cta_group::1.sync.aligned.b32 %0, %1;" :: "r"(tmem), "r"(ncols));
}
__device__ __forceinline__ void tc_commit(uint32_t mbar) {
    asm volatile("tcgen05.commit.cta_group::1.mbarrier::arrive::one.shared::cluster.b64 [%0];"
                 :: "r"(mbar) : "memory");
}
__device__ __forceinline__ void mma_f16_ss(uint32_t d, uint64_t a, uint64_t b,
                                           uint32_t idesc, uint32_t en) {
    asm volatile(
        "{\n\t.reg .pred p;\n\t"
        "setp.ne.u32 p, %5, 0;\n\t"
        "tcgen05.mma.cta_group::1.kind::f16 [%0], %1, %2, %3, {%4, %4, %4, %4}, p;\n\t}"
        :: "r"(d), "l"(a), "l"(b), "r"(idesc), "r"(0u), "r"(en) : "memory");
}
__device__ __forceinline__ void tmem_ld_x32(uint32_t* r, uint32_t addr) {
    asm volatile(
        "tcgen05.ld.sync.aligned.32x32b.x32.b32 "
        "{%0,%1,%2,%3,%4,%5,%6,%7,%8,%9,%10,%11,%12,%13,%14,%15,"
        "%16,%17,%18,%19,%20,%21,%22,%23,%24,%25,%26,%27,%28,%29,%30,%31}, [%32];"
        : "=r"(r[0]), "=r"(r[1]), "=r"(r[2]), "=r"(r[3]), "=r"(r[4]), "=r"(r[5]), "=r"(r[6]), "=r"(r[7]),
          "=r"(r[8]), "=r"(r[9]), "=r"(r[10]), "=r"(r[11]), "=r"(r[12]), "=r"(r[13]), "=r"(r[14]), "=r"(r[15]),
          "=r"(r[16]), "=r"(r[17]), "=r"(r[18]), "=r"(r[19]), "=r"(r[20]), "=r"(r[21]), "=r"(r[22]), "=r"(r[23]),
          "=r"(r[24]), "=r"(r[25]), "=r"(r[26]), "=r"(r[27]), "=r"(r[28]), "=r"(r[29]), "=r"(r[30]), "=r"(r[31])
        : "r"(addr));
}
__device__ __forceinline__ void tmem_wait_ld() {
    asm volatile("tcgen05.wait::ld.sync.aligned;" ::: "memory");
}
__device__ __forceinline__ void fence_async_shared() {
    asm volatile("fence.proxy.async.shared::cta;" ::: "memory");
}
__device__ __forceinline__ void tc_fence_after() {
    asm volatile("tcgen05.fence::after_thread_sync;" ::: "memory");
}
static constexpr uint64_t DESC_BASE_SW128 =
    (uint64_t(2) << 61) | (uint64_t(1) << 46) | (uint64_t(64) << 32) | (uint64_t(1) << 16);
__device__ __forceinline__ uint64_t make_desc(uint32_t addr) {
    return DESC_BASE_SW128 | ((uint64_t)(addr >> 4) & 0x3FFF);
}
#define IDESC_128x128 0x8200490u
#else
// ---------------------------------------------------------------------------
// Portable tensor path: mma.sync bf16 (HMMA) helpers
// ---------------------------------------------------------------------------
__device__ __forceinline__ void ldsm4(uint32_t* r, uint32_t addr) {
    asm volatile("ldmatrix.sync.aligned.m8n8.x4.shared.b16 {%0,%1,%2,%3}, [%4];"
                 : "=r"(r[0]), "=r"(r[1]), "=r"(r[2]), "=r"(r[3]) : "r"(addr));
}
__device__ __forceinline__ void mma_bf16(float* c, const uint32_t* a, uint32_t b0, uint32_t b1) {
    asm volatile("mma.sync.aligned.m16n8k16.row.col.f32.bf16.bf16.f32 "
                 "{%0,%1,%2,%3}, {%4,%5,%6,%7}, {%8,%9}, {%0,%1,%2,%3};"
                 : "+f"(c[0]), "+f"(c[1]), "+f"(c[2]), "+f"(c[3])
                 : "r"(a[0]), "r"(a[1]), "r"(a[2]), "r"(a[3]), "r"(b0), "r"(b1));
}
#endif

// ---------------------------------------------------------------------------
// Tensor-core GEMM: C[m,n] = sum_k A[m,k]*B[n,k], 128x128 CTA tile, BK=64,
// bf16 hi/lo split (3 chains), fp32 accumulate.
// ---------------------------------------------------------------------------
#define SMEM_BYTES (1024 + 2 * 65536)

template <bool TA, bool TB>
__global__ void __launch_bounds__(256, 1)
tc_gemm(const float* __restrict__ gA, const float* __restrict__ gB, float* __restrict__ gC,
        int K, int lda, int ldb, int ldc, long long sA, long long sB, long long sC)
{
    extern __shared__ char smem[];
    const uint32_t sb = smem_u32(smem);
    const int tid = threadIdx.x, wid = tid >> 5, lane = tid & 31;
    const float* A = gA + (long long)blockIdx.z * sA;
    const float* B = gB + (long long)blockIdx.z * sB;
    float* C = gC + (long long)blockIdx.z * sC;
    const int m0 = blockIdx.y * 128, n0 = blockIdx.x * 128;
    const int NKT = K >> 6;

#if defined(__CUDA_ARCH_FEAT_SM103_ALL)
    if (tid == 0) mbar_init(sb, 1);
    if (wid == 0) { tmem_alloc(sb + 8, 128); tmem_relinq(); }
    __syncthreads();
    uint32_t tmem;
    asm volatile("ld.shared.b32 %0, [%1];" : "=r"(tmem) : "r"(sb + 8));

    load_tile<TA>(A, lda, m0, 0, sb + 1024, sb + 1024 + 16384, tid);
    load_tile<TB>(B, ldb, n0, 0, sb + 1024 + 32768, sb + 1024 + 49152, tid);
    fence_async_shared();
    __syncthreads();

    for (int kt = 0; kt < NKT; kt++) {
        const uint32_t tb = sb + 1024 + (uint32_t)(kt & 1) * 65536;
        if (wid == 0 && elect1()) {
            uint64_t ah = make_desc(tb);
            uint64_t al = make_desc(tb + 16384);
            uint64_t bh = make_desc(tb + 32768);
            uint64_t bl = make_desc(tb + 49152);
            uint32_t en = (kt > 0) ? 1u : 0u;
#pragma unroll
            for (int ks = 0; ks < 4; ks++) {
                mma_f16_ss(tmem, ah + ks * 2, bh + ks * 2, IDESC_128x128, en); en = 1;
                mma_f16_ss(tmem, ah + ks * 2, bl + ks * 2, IDESC_128x128, 1);
                mma_f16_ss(tmem, al + ks * 2, bh + ks * 2, IDESC_128x128, 1);
            }
            tc_commit(sb);
        }
        if (kt >= 1) mbar_wait(sb, (uint32_t)((kt - 1) & 1));
        if (kt + 1 < NKT) {
            const uint32_t nb = sb + 1024 + (uint32_t)((kt + 1) & 1) * 65536;
            load_tile<TA>(A, lda, m0, (kt + 1) * 64, nb, nb + 16384, tid);
            load_tile<TB>(B, ldb, n0, (kt + 1) * 64, nb + 32768, nb + 49152, tid);
            fence_async_shared();
        }
        __syncthreads();
    }
    mbar_wait(sb, (uint32_t)((NKT - 1) & 1));
    tc_fence_after();

    if (wid < 4) {
        const int row = m0 + wid * 32 + lane;
#pragma unroll
        for (int c0 = 0; c0 < 128; c0 += 32) {
            uint32_t r[32];
            tmem_ld_x32(r, tmem + c0);
            tmem_wait_ld();
            float* cp = &C[(long long)row * ldc + n0 + c0];
#pragma unroll
            for (int q = 0; q < 8; q++) {
                *(float4*)(cp + q * 4) = make_float4(
                    __uint_as_float(r[q * 4 + 0]), __uint_as_float(r[q * 4 + 1]),
                    __uint_as_float(r[q * 4 + 2]), __uint_as_float(r[q * 4 + 3]));
            }
        }
    }
    __syncthreads();
    if (wid == 0) {
        if (elect1()) mbar_inval(sb);
        tmem_dealloc(tmem, 128);
    }
#else
    // ---------------- HMMA path (mma.sync bf16) ----------------
    const int wm = wid >> 1;      // 0..3 -> 32 rows each
    const int wn = wid & 1;       // 0..1 -> 64 cols each
    float acc[2][8][4];
#pragma unroll
    for (int t = 0; t < 2; t++)
#pragma unroll
        for (int q = 0; q < 8; q++)
#pragma unroll
            for (int e = 0; e < 4; e++) acc[t][q][e] = 0.f;

    // A frag ldmatrix addr pattern (16x16): row = base + (lane&15), colB = ks*32 + (lane>>4)*16
    const int a_r = lane & 15;
    const int a_c = (lane >> 4) * 16;
    // B frag (n16 x k16): row = base + (lane&7) + ((lane>>4)<<3), colB = ks*32 + ((lane>>3)&1)*16
    const int b_r = (lane & 7) + ((lane >> 4) << 3);
    const int b_c = ((lane >> 3) & 1) * 16;

    load_tile<TA>(A, lda, m0, 0, sb + 1024, sb + 1024 + 16384, tid);
    load_tile<TB>(B, ldb, n0, 0, sb + 1024 + 32768, sb + 1024 + 49152, tid);
    __syncthreads();

    for (int kt = 0; kt < NKT; kt++) {
        const uint32_t tb = sb + 1024 + (uint32_t)(kt & 1) * 65536;
        const uint32_t sAh = tb, sAl = tb + 16384, sBh = tb + 32768, sBl = tb + 49152;
#pragma unroll
        for (int ks = 0; ks < 4; ks++) {
            uint32_t a_hi[2][4], a_lo[2][4], b_hi[4][4], b_lo[4][4];
#pragma unroll
            for (int t = 0; t < 2; t++) {
                uint32_t off = (uint32_t)((wm * 32 + t * 16 + a_r) * 128 + ks * 32 + a_c);
                ldsm4(a_hi[t], sAh + swz(off));
                ldsm4(a_lo[t], sAl + swz(off));
            }
#pragma unroll
            for (int p = 0; p < 4; p++) {
                uint32_t off = (uint32_t)((wn * 64 + p * 16 + b_r) * 128 + ks * 32 + b_c);
                ldsm4(b_hi[p], sBh + swz(off));
                ldsm4(b_lo[p], sBl + swz(off));
            }
#pragma unroll
            for (int t = 0; t < 2; t++)
#pragma unroll
                for (int q = 0; q < 8; q++) {
                    const int p = q >> 1, h = (q & 1) * 2;
                    mma_bf16(acc[t][q], a_hi[t], b_hi[p][h], b_hi[p][h + 1]);
                    mma_bf16(acc[t][q], a_hi[t], b_lo[p][h], b_lo[p][h + 1]);
                    mma_bf16(acc[t][q], a_lo[t], b_hi[p][h], b_hi[p][h + 1]);
                }
            if (ks == 0 && kt + 1 < NKT) {
                const uint32_t nb = sb + 1024 + (uint32_t)((kt + 1) & 1) * 65536;
                load_tile<TA>(A, lda, m0, (kt + 1) * 64, nb, nb + 16384, tid);
                load_tile<TB>(B, ldb, n0, (kt + 1) * 64, nb + 32768, nb + 49152, tid);
            }
        }
        __syncthreads();
    }

    // epilogue: acc thread map (m16n8): c0,c1 = (row0, col0..1), c2,c3 = (row0+8, ...)
    const int row0 = lane >> 2, col0 = (lane & 3) * 2;
#pragma unroll
    for (int t = 0; t < 2; t++) {
        const int r = m0 + wm * 32 + t * 16 + row0;
#pragma unroll
        for (int q = 0; q < 8; q++) {
            const int c = n0 + wn * 64 + q * 8 + col0;
            *(float2*)&C[(long long)r * ldc + c] = make_float2(acc[t][q][0], acc[t][q][1]);
            *(float2*)&C[(long long)(r + 8) * ldc + c] = make_float2(acc[t][q][2], acc[t][q][3]);
        }
    }
#endif
}

// ---------------------------------------------------------------------------
// Row-direction masked softmax
// ---------------------------------------------------------------------------
__global__ __launch_bounds__(256)
void row_softmax_kernel(const float* __restrict__ S, float* __restrict__ P,
                        const float* __restrict__ pmask, const float* __restrict__ hmask)
{
    const int i = blockIdx.x;
    const int b = blockIdx.y;
    const long long rowoff = ((long long)b * LA + i) * LB;
    const int tid = threadIdx.x;

    float4 s = *(const float4*)&S[rowoff + tid * 4];
    float4 h = *(const float4*)&hmask[(long long)b * LB + tid * 4];
    float l0 = s.x * h.x, l1 = s.y * h.y, l2 = s.z * h.z, l3 = s.w * h.w;

    __shared__ float redA[8], redB[8];

    float v = fmaxf(fmaxf(l0, l1), fmaxf(l2, l3));
#pragma unroll
    for (int o = 16; o; o >>= 1) v = fmaxf(v, __shfl_xor_sync(0xffffffffu, v, o));
    if ((tid & 31) == 0) redA[tid >> 5] = v;
    __syncthreads();
    float m = redA[0];
#pragma unroll
    for (int w = 1; w < 8; w++) m = fmaxf(m, redA[w]);
    __syncthreads();

    float e0 = __expf(l0 - m), e1 = __expf(l1 - m), e2 = __expf(l2 - m), e3 = __expf(l3 - m);
    float d = e0 + e1 + e2 + e3;
    float e = h.x * e0 + h.y * e1 + h.z * e2 + h.w * e3;
#pragma unroll
    for (int o = 16; o; o >>= 1) {
        d += __shfl_xor_sync(0xffffffffu, d, o);
        e += __shfl_xor_sync(0xffffffffu, e, o);
    }
    if ((tid & 31) == 0) { redA[tid >> 5] = d; redB[tid >> 5] = e; }
    __syncthreads();
    float D = 0.f, E = 0.f;
#pragma unroll
    for (int w = 0; w < 8; w++) { D += redA[w]; E += redB[w]; }

    const float pm = pmask[(long long)b * LA + i];
    const float scale = pm / (E + EPSV * D);

    float4 o4 = make_float4(h.x * e0 * scale, h.y * e1 * scale,
                            h.z * e2 * scale, h.w * e3 * scale);
    *(float4*)&P[rowoff + tid * 4] = o4;
}

// ---------------------------------------------------------------------------
// Column-direction masked softmax
// ---------------------------------------------------------------------------
__global__ __launch_bounds__(256)
void col_softmax_kernel(const float* __restrict__ S, float* __restrict__ P,
                        const float* __restrict__ pmask, const float* __restrict__ hmask)
{
    const int b = blockIdx.y;
    const int tx = threadIdx.x & 31;
    const int ty = threadIdx.x >> 5;
    const int j = blockIdx.x * 32 + tx;
    const float* Sb = S + (long long)b * LA * LB;
    float* Pb = P + (long long)b * LA * LB;
    const float* pm = pmask + (long long)b * LA;

    __shared__ float red[8][32];

    float mx = -1e30f;
    for (int r = ty; r < LA; r += 8) {
        float l = Sb[(long long)r * LB + j] * pm[r];
        mx = fmaxf(mx, l);
    }
    red[ty][tx] = mx;
    __syncthreads();
    mx = red[0][tx];
#pragma unroll
    for (int t = 1; t < 8; t++) mx = fmaxf(mx, red[t][tx]);
    __syncthreads();

    float D = 0.f, E = 0.f;
    for (int r = ty; r < LA; r += 8) {
        float pmr = pm[r];
        float ev = __expf(Sb[(long long)r * LB + j] * pmr - mx);
        D += ev;
        E += pmr * ev;
    }
    red[ty][tx] = D;
    __syncthreads();
    D = 0.f;
#pragma unroll
    for (int t = 0; t < 8; t++) D += red[t][tx];
    __syncthreads();
    red[ty][tx] = E;
    __syncthreads();
    E = 0.f;
#pragma unroll
    for (int t = 0; t < 8; t++) E += red[t][tx];
    __syncthreads();

    const float scale = hmask[(long long)b * LB + j] / (E + EPSV * D);

    for (int r = ty; r < LA; r += 8) {
        float pmr = pm[r];
        float ev = __expf(Sb[(long long)r * LB + j] * pmr - mx);
        Pb[(long long)r * LB + j] = pmr * ev * scale;
    }
}

// ---------------------------------------------------------------------------
extern "C" void kernel_launch(void* const* d_in, const int* in_sizes, int n_in,
                              void* d_out, int out_size)
{
    const float* prem  = (const float*)d_in[0];  // [16,1024,512]
    const float* pmask = (const float*)d_in[1];  // [16,1024]
    const float* hyp   = (const float*)d_in[2];  // [16,1024,512]
    const float* hmask = (const float*)d_in[3];  // [16,1024]

    float* AP = (float*)d_out;                    // [16,1024,512]
    float* AH = AP + (long long)NB * LA * HD;     // [16,1024,512]

    void* pS; cudaGetSymbolAddress(&pS, g_S);
    void* pP; cudaGetSymbolAddress(&pP, g_P);
    float* S = (float*)pS;
    float* P = (float*)pP;

    const long long sAB = (long long)LA * HD;
    const long long sS  = (long long)LA * LB;

    cudaFuncSetAttribute(tc_gemm<false, false>, cudaFuncAttributeMaxDynamicSharedMemorySize, SMEM_BYTES);
    cudaFuncSetAttribute(tc_gemm<false, true>,  cudaFuncAttributeMaxDynamicSharedMemorySize, SMEM_BYTES);
    cudaFuncSetAttribute(tc_gemm<true, true>,   cudaFuncAttributeMaxDynamicSharedMemorySize, SMEM_BYTES);

    // 1) S = premise @ hypothesis^T   (M=1024, N=1024, K=512; both K-major)
    {
        dim3 grid(LB / 128, LA / 128, NB);
        tc_gemm<false, false><<<grid, 256, SMEM_BYTES>>>(prem, hyp, S, HD, HD, HD, LB, sAB, sAB, sS);
    }
    // 2) row masked-softmax -> P (pmask folded in)
    {
        dim3 grid(LA, NB);
        row_softmax_kernel<<<grid, 256>>>(S, P, pmask, hmask);
    }
    // 3) AP = P @ hyp   (M=1024, N=512, K=1024; B = hyp^T via transposed load)
    {
        dim3 grid(HD / 128, LA / 128, NB);
        tc_gemm<false, true><<<grid, 256, SMEM_BYTES>>>(P, hyp, AP, LB, LB, HD, HD, sS, sAB, sAB);
    }
    // 4) column masked-softmax -> P (hmask folded in)
    {
        dim3 grid(LB / 32, NB);
        col_softmax_kernel<<<grid, 256>>>(S, P, pmask, hmask);
    }
    // 5) AH = P^T @ prem  (M=1024(j), N=512, K=1024(i); both transposed loads)
    {
        dim3 grid(HD / 128, LB / 128, NB);
        tc_gemm<true, true><<<grid, 256, SMEM_BYTES>>>(P, prem, AH, LA, LA, HD, HD, sS, sAB, sAB);
    }
}

// round 6
// speedup vs baseline: 2.5121x; 1.1457x over previous
#include <cuda_runtime.h>
#include <cuda_bf16.h>
#include <cstdint>

#define NB 16
#define LA 1024
#define LB 1024
#define HD 512
#define EPSV 1e-13f

// fp32 scratch (logits) + bf16 hi/lo operand caches
__device__ float         g_S [(long long)NB * LA * LB];
__device__ __nv_bfloat16 g_PH[(long long)NB * LA * LB];   // row-softmax out hi
__device__ __nv_bfloat16 g_PL[(long long)NB * LA * LB];   // row-softmax out lo
__device__ __nv_bfloat16 g_QH[(long long)NB * LA * LB];   // col-softmax out hi
__device__ __nv_bfloat16 g_QL[(long long)NB * LA * LB];   // col-softmax out lo
__device__ __nv_bfloat16 g_pmH[(long long)NB * LA * HD];  // prem hi
__device__ __nv_bfloat16 g_pmL[(long long)NB * LA * HD];  // prem lo
__device__ __nv_bfloat16 g_hyH[(long long)NB * LB * HD];  // hyp hi
__device__ __nv_bfloat16 g_hyL[(long long)NB * LB * HD];  // hyp lo

// ---------------------------------------------------------------------------
// helpers
// ---------------------------------------------------------------------------
__device__ __forceinline__ uint32_t smem_u32(const void* p) {
    uint32_t a;
    asm("{ .reg .u64 t; cvta.to.shared.u64 t, %1; cvt.u32.u64 %0, t; }" : "=r"(a) : "l"(p));
    return a;
}
__device__ __forceinline__ uint32_t swz128(uint32_t off) { return off ^ ((off >> 3) & 0x70); }
__device__ __forceinline__ uint32_t swz256(uint32_t off) { return off ^ ((off >> 4) & 0x70); }

__device__ __forceinline__ void cp16(uint32_t dst, const void* src) {
    asm volatile("cp.async.cg.shared.global [%0], [%1], 16;" :: "r"(dst), "l"(src));
}
__device__ __forceinline__ void cp_commit() { asm volatile("cp.async.commit_group;"); }
__device__ __forceinline__ void cp_wait0()  { asm volatile("cp.async.wait_group 0;" ::: "memory"); }

__device__ __forceinline__ void ldsm4(uint32_t* r, uint32_t addr) {
    asm volatile("ldmatrix.sync.aligned.m8n8.x4.shared.b16 {%0,%1,%2,%3}, [%4];"
                 : "=r"(r[0]), "=r"(r[1]), "=r"(r[2]), "=r"(r[3]) : "r"(addr));
}
__device__ __forceinline__ void ldsm4t(uint32_t* r, uint32_t addr) {
    asm volatile("ldmatrix.sync.aligned.m8n8.x4.trans.shared.b16 {%0,%1,%2,%3}, [%4];"
                 : "=r"(r[0]), "=r"(r[1]), "=r"(r[2]), "=r"(r[3]) : "r"(addr));
}
__device__ __forceinline__ void mma_bf16(float* c, const uint32_t* a, uint32_t b0, uint32_t b1) {
    asm volatile("mma.sync.aligned.m16n8k16.row.col.f32.bf16.bf16.f32 "
                 "{%0,%1,%2,%3}, {%4,%5,%6,%7}, {%8,%9}, {%0,%1,%2,%3};"
                 : "+f"(c[0]), "+f"(c[1]), "+f"(c[2]), "+f"(c[3])
                 : "r"(a[0]), "r"(a[1]), "r"(a[2]), "r"(a[3]), "r"(b0), "r"(b1));
}

// ---------------------------------------------------------------------------
// fp32 -> bf16 hi/lo split (elementwise)
// ---------------------------------------------------------------------------
__global__ __launch_bounds__(256)
void split_kernel(const float* __restrict__ src, __nv_bfloat16* __restrict__ oh,
                  __nv_bfloat16* __restrict__ ol)
{
    long long i = ((long long)blockIdx.x * 256 + threadIdx.x) * 4;
    float4 v = *(const float4*)(src + i);
    __nv_bfloat162 h01 = __floats2bfloat162_rn(v.x, v.y);
    __nv_bfloat162 h23 = __floats2bfloat162_rn(v.z, v.w);
    __nv_bfloat162 l01 = __floats2bfloat162_rn(v.x - __bfloat162float(h01.x),
                                               v.y - __bfloat162float(h01.y));
    __nv_bfloat162 l23 = __floats2bfloat162_rn(v.z - __bfloat162float(h23.x),
                                               v.w - __bfloat162float(h23.y));
    *(uint2*)(oh + i) = make_uint2(*(uint32_t*)&h01, *(uint32_t*)&h23);
    *(uint2*)(ol + i) = make_uint2(*(uint32_t*)&l01, *(uint32_t*)&l23);
}

// ---------------------------------------------------------------------------
// tile loader: bf16 gmem -> swizzled smem via cp.async (16B chunks)
// MODE 0: K-major  (x rows, 64 k each, 128B pitch, swz128); src[x][k], pitch ld
// MODE 1: MN-major (64 k rows, 128 x each, 256B pitch, swz256); src[k][x], pitch ld
// ---------------------------------------------------------------------------
template <int MODE>
__device__ __forceinline__ void load_op(const __nv_bfloat16* __restrict__ src, int ld,
                                        int x0, int k0, uint32_t dstb, int tid) {
    if (MODE == 0) {
#pragma unroll
        for (int it = 0; it < 4; it++) {
            int u = it * 256 + tid;
            int x = u >> 3, c = u & 7;
            cp16(dstb + swz128((uint32_t)(x * 128 + c * 16)),
                 src + (long long)(x0 + x) * ld + k0 + c * 8);
        }
    } else {
#pragma unroll
        for (int it = 0; it < 4; it++) {
            int u = it * 256 + tid;
            int k = u >> 4, c = u & 15;
            cp16(dstb + swz256((uint32_t)(k * 256 + c * 16)),
                 src + (long long)(k0 + k) * ld + x0 + c * 8);
        }
    }
}

// ---------------------------------------------------------------------------
// HMMA GEMM: C[m,n] = sum_k A[m,k]*B[n,k]; 128x128 CTA tile, BK=64,
// bf16 hi/lo 3-chain, fp32 accum. AMODE/BMODE: 0 = K-major smem + ldmatrix,
// 1 = MN-major smem + ldmatrix.trans.
// ---------------------------------------------------------------------------
#define SMEM_BYTES (2 * 65536)

template <int AMODE, int BMODE>
__global__ void __launch_bounds__(256, 1)
tc_gemm(const __nv_bfloat16* __restrict__ gAH, const __nv_bfloat16* __restrict__ gAL,
        const __nv_bfloat16* __restrict__ gBH, const __nv_bfloat16* __restrict__ gBL,
        float* __restrict__ gC,
        int K, int lda, int ldb, int ldc, long long sA, long long sB, long long sC)
{
    extern __shared__ char smem[];
    const uint32_t sb = smem_u32(smem);
    const int tid = threadIdx.x, wid = tid >> 5, lane = tid & 31;
    const __nv_bfloat16* AH = gAH + (long long)blockIdx.z * sA;
    const __nv_bfloat16* AL = gAL + (long long)blockIdx.z * sA;
    const __nv_bfloat16* BH = gBH + (long long)blockIdx.z * sB;
    const __nv_bfloat16* BL = gBL + (long long)blockIdx.z * sB;
    float* C = gC + (long long)blockIdx.z * sC;
    const int m0 = blockIdx.y * 128, n0 = blockIdx.x * 128;
    const int NKT = K >> 6;

    const int wm = wid >> 1;   // 0..3 (32 m-rows each)
    const int wn = wid & 1;    // 0..1 (64 n-cols each)
    float acc[2][8][4];
#pragma unroll
    for (int t = 0; t < 2; t++)
#pragma unroll
        for (int q = 0; q < 8; q++)
#pragma unroll
            for (int e = 0; e < 4; e++) acc[t][q][e] = 0.f;

    // fragment smem offsets (per ks/t/p added later)
    // A non-trans:  (wm*32 + t*16 + (lane&15))*128 + ks*32 + (lane>>4)*16   [swz128]
    // A trans:      (ks*16 + (lane&7) + ((lane>>4)&1)*8)*256
    //                + (wm*32 + t*16 + ((lane>>3)&1)*8)*2                   [swz256]
    // B non-trans:  (wn*64 + p*16 + (lane&7) + ((lane>>4)<<3))*128 + ks*32
    //                + ((lane>>3)&1)*16                                     [swz128]
    // B trans:      (ks*16 + (lane&15))*256 + (wn*64 + p*16 + (lane>>4)*8)*2 [swz256]

    // prologue
    {
        uint32_t b0 = sb;
        load_op<AMODE>(AH, lda, m0, 0, b0 + 0,     tid);
        load_op<AMODE>(AL, lda, m0, 0, b0 + 16384, tid);
        load_op<BMODE>(BH, ldb, n0, 0, b0 + 32768, tid);
        load_op<BMODE>(BL, ldb, n0, 0, b0 + 49152, tid);
        cp_commit();
    }

    int buf = 0;
    for (int kt = 0; kt < NKT; kt++) {
        cp_wait0();
        __syncthreads();
        if (kt + 1 < NKT) {
            uint32_t nb = sb + (uint32_t)(buf ^ 1) * 65536;
            int k0 = (kt + 1) * 64;
            load_op<AMODE>(AH, lda, m0, k0, nb + 0,     tid);
            load_op<AMODE>(AL, lda, m0, k0, nb + 16384, tid);
            load_op<BMODE>(BH, ldb, n0, k0, nb + 32768, tid);
            load_op<BMODE>(BL, ldb, n0, k0, nb + 49152, tid);
            cp_commit();
        }
        const uint32_t tb = sb + (uint32_t)buf * 65536;
        const uint32_t sAh = tb, sAl = tb + 16384, sBh = tb + 32768, sBl = tb + 49152;
#pragma unroll
        for (int ks = 0; ks < 4; ks++) {
            uint32_t a_hi[2][4], a_lo[2][4], b_hi[4][4], b_lo[4][4];
#pragma unroll
            for (int t = 0; t < 2; t++) {
                if (AMODE == 0) {
                    uint32_t off = (uint32_t)((wm * 32 + t * 16 + (lane & 15)) * 128
                                              + ks * 32 + (lane >> 4) * 16);
                    uint32_t sw = swz128(off);
                    ldsm4(a_hi[t], sAh + sw);
                    ldsm4(a_lo[t], sAl + sw);
                } else {
                    uint32_t off = (uint32_t)((ks * 16 + (lane & 7) + ((lane >> 4) & 1) * 8) * 256
                                              + (wm * 32 + t * 16 + ((lane >> 3) & 1) * 8) * 2);
                    uint32_t sw = swz256(off);
                    ldsm4t(a_hi[t], sAh + sw);
                    ldsm4t(a_lo[t], sAl + sw);
                }
            }
#pragma unroll
            for (int p = 0; p < 4; p++) {
                if (BMODE == 0) {
                    uint32_t off = (uint32_t)((wn * 64 + p * 16 + (lane & 7) + ((lane >> 4) << 3)) * 128
                                              + ks * 32 + ((lane >> 3) & 1) * 16);
                    uint32_t sw = swz128(off);
                    ldsm4(b_hi[p], sBh + sw);
                    ldsm4(b_lo[p], sBl + sw);
                } else {
                    uint32_t off = (uint32_t)((ks * 16 + (lane & 15)) * 256
                                              + (wn * 64 + p * 16 + (lane >> 4) * 8) * 2);
                    uint32_t sw = swz256(off);
                    ldsm4t(b_hi[p], sBh + sw);
                    ldsm4t(b_lo[p], sBl + sw);
                }
            }
#pragma unroll
            for (int t = 0; t < 2; t++)
#pragma unroll
                for (int q = 0; q < 8; q++) {
                    const int p = q >> 1, h = (q & 1) * 2;
                    mma_bf16(acc[t][q], a_hi[t], b_hi[p][h], b_hi[p][h + 1]);
                    mma_bf16(acc[t][q], a_hi[t], b_lo[p][h], b_lo[p][h + 1]);
                    mma_bf16(acc[t][q], a_lo[t], b_hi[p][h], b_hi[p][h + 1]);
                }
        }
        buf ^= 1;
        __syncthreads();
    }

    // epilogue
    const int row0 = lane >> 2, col0 = (lane & 3) * 2;
#pragma unroll
    for (int t = 0; t < 2; t++) {
        const int r = m0 + wm * 32 + t * 16 + row0;
#pragma unroll
        for (int q = 0; q < 8; q++) {
            const int c = n0 + wn * 64 + q * 8 + col0;
            *(float2*)&C[(long long)r * ldc + c] = make_float2(acc[t][q][0], acc[t][q][1]);
            *(float2*)&C[(long long)(r + 8) * ldc + c] = make_float2(acc[t][q][2], acc[t][q][3]);
        }
    }
}

// ---------------------------------------------------------------------------
// Row-direction masked softmax -> bf16 hi/lo
// ---------------------------------------------------------------------------
__global__ __launch_bounds__(256)
void row_softmax_kernel(const float* __restrict__ S,
                        __nv_bfloat16* __restrict__ PH, __nv_bfloat16* __restrict__ PL,
                        const float* __restrict__ pmask, const float* __restrict__ hmask)
{
    const int i = blockIdx.x;
    const int b = blockIdx.y;
    const long long rowoff = ((long long)b * LA + i) * LB;
    const int tid = threadIdx.x;

    float4 s = *(const float4*)&S[rowoff + tid * 4];
    float4 h = *(const float4*)&hmask[(long long)b * LB + tid * 4];
    float l0 = s.x * h.x, l1 = s.y * h.y, l2 = s.z * h.z, l3 = s.w * h.w;

    __shared__ float redA[8], redB[8];

    float v = fmaxf(fmaxf(l0, l1), fmaxf(l2, l3));
#pragma unroll
    for (int o = 16; o; o >>= 1) v = fmaxf(v, __shfl_xor_sync(0xffffffffu, v, o));
    if ((tid & 31) == 0) redA[tid >> 5] = v;
    __syncthreads();
    float m = redA[0];
#pragma unroll
    for (int w = 1; w < 8; w++) m = fmaxf(m, redA[w]);
    __syncthreads();

    float e0 = __expf(l0 - m), e1 = __expf(l1 - m), e2 = __expf(l2 - m), e3 = __expf(l3 - m);
    float d = e0 + e1 + e2 + e3;
    float e = h.x * e0 + h.y * e1 + h.z * e2 + h.w * e3;
#pragma unroll
    for (int o = 16; o; o >>= 1) {
        d += __shfl_xor_sync(0xffffffffu, d, o);
        e += __shfl_xor_sync(0xffffffffu, e, o);
    }
    if ((tid & 31) == 0) { redA[tid >> 5] = d; redB[tid >> 5] = e; }
    __syncthreads();
    float D = 0.f, E = 0.f;
#pragma unroll
    for (int w = 0; w < 8; w++) { D += redA[w]; E += redB[w]; }

    const float pm = pmask[(long long)b * LA + i];
    const float scale = pm / (E + EPSV * D);

    float v0 = h.x * e0 * scale, v1 = h.y * e1 * scale;
    float v2 = h.z * e2 * scale, v3 = h.w * e3 * scale;
    __nv_bfloat162 h01 = __floats2bfloat162_rn(v0, v1);
    __nv_bfloat162 h23 = __floats2bfloat162_rn(v2, v3);
    __nv_bfloat162 q01 = __floats2bfloat162_rn(v0 - __bfloat162float(h01.x),
                                               v1 - __bfloat162float(h01.y));
    __nv_bfloat162 q23 = __floats2bfloat162_rn(v2 - __bfloat162float(h23.x),
                                               v3 - __bfloat162float(h23.y));
    *(uint2*)&PH[rowoff + tid * 4] = make_uint2(*(uint32_t*)&h01, *(uint32_t*)&h23);
    *(uint2*)&PL[rowoff + tid * 4] = make_uint2(*(uint32_t*)&q01, *(uint32_t*)&q23);
}

// ---------------------------------------------------------------------------
// Column-direction masked softmax -> bf16 hi/lo (output stays [i][j] layout)
// ---------------------------------------------------------------------------
__global__ __launch_bounds__(256)
void col_softmax_kernel(const float* __restrict__ S,
                        __nv_bfloat16* __restrict__ QH, __nv_bfloat16* __restrict__ QL,
                        const float* __restrict__ pmask, const float* __restrict__ hmask)
{
    const int b = blockIdx.y;
    const int tx = threadIdx.x & 31;
    const int ty = threadIdx.x >> 5;
    const int j = blockIdx.x * 32 + tx;
    const float* Sb = S + (long long)b * LA * LB;
    __nv_bfloat16* Qh = QH + (long long)b * LA * LB;
    __nv_bfloat16* Ql = QL + (long long)b * LA * LB;
    const float* pm = pmask + (long long)b * LA;

    __shared__ float red[8][32];

    float mx = -1e30f;
    for (int r = ty; r < LA; r += 8) {
        float l = Sb[(long long)r * LB + j] * pm[r];
        mx = fmaxf(mx, l);
    }
    red[ty][tx] = mx;
    __syncthreads();
    mx = red[0][tx];
#pragma unroll
    for (int t = 1; t < 8; t++) mx = fmaxf(mx, red[t][tx]);
    __syncthreads();

    float D = 0.f, E = 0.f;
    for (int r = ty; r < LA; r += 8) {
        float pmr = pm[r];
        float ev = __expf(Sb[(long long)r * LB + j] * pmr - mx);
        D += ev;
        E += pmr * ev;
    }
    red[ty][tx] = D;
    __syncthreads();
    D = 0.f;
#pragma unroll
    for (int t = 0; t < 8; t++) D += red[t][tx];
    __syncthreads();
    red[ty][tx] = E;
    __syncthreads();
    E = 0.f;
#pragma unroll
    for (int t = 0; t < 8; t++) E += red[t][tx];
    __syncthreads();

    const float scale = hmask[(long long)b * LB + j] / (E + EPSV * D);

    for (int r = ty; r < LA; r += 8) {
        float pmr = pm[r];
        float ev = __expf(Sb[(long long)r * LB + j] * pmr - mx);
        float val = pmr * ev * scale;
        __nv_bfloat16 hh = __float2bfloat16_rn(val);
        __nv_bfloat16 ll = __float2bfloat16_rn(val - __bfloat162float(hh));
        Qh[(long long)r * LB + j] = hh;
        Ql[(long long)r * LB + j] = ll;
    }
}

// ---------------------------------------------------------------------------
extern "C" void kernel_launch(void* const* d_in, const int* in_sizes, int n_in,
                              void* d_out, int out_size)
{
    const float* prem  = (const float*)d_in[0];  // [16,1024,512]
    const float* pmask = (const float*)d_in[1];  // [16,1024]
    const float* hyp   = (const float*)d_in[2];  // [16,1024,512]
    const float* hmask = (const float*)d_in[3];  // [16,1024]

    float* AP = (float*)d_out;                    // [16,1024,512]
    float* AH = AP + (long long)NB * LA * HD;     // [16,1024,512]

    void *pS, *pPH, *pPL, *pQH, *pQL, *ppmH, *ppmL, *phyH, *phyL;
    cudaGetSymbolAddress(&pS, g_S);
    cudaGetSymbolAddress(&pPH, g_PH);  cudaGetSymbolAddress(&pPL, g_PL);
    cudaGetSymbolAddress(&pQH, g_QH);  cudaGetSymbolAddress(&pQL, g_QL);
    cudaGetSymbolAddress(&ppmH, g_pmH); cudaGetSymbolAddress(&ppmL, g_pmL);
    cudaGetSymbolAddress(&phyH, g_hyH); cudaGetSymbolAddress(&phyL, g_hyL);
    float* S = (float*)pS;
    __nv_bfloat16 *PH = (__nv_bfloat16*)pPH, *PL = (__nv_bfloat16*)pPL;
    __nv_bfloat16 *QH = (__nv_bfloat16*)pQH, *QL = (__nv_bfloat16*)pQL;
    __nv_bfloat16 *pmH = (__nv_bfloat16*)ppmH, *pmL = (__nv_bfloat16*)ppmL;
    __nv_bfloat16 *hyH = (__nv_bfloat16*)phyH, *hyL = (__nv_bfloat16*)phyL;

    const long long sAB = (long long)LA * HD;   // 524288
    const long long sS  = (long long)LA * LB;   // 1048576

    cudaFuncSetAttribute(tc_gemm<0, 0>, cudaFuncAttributeMaxDynamicSharedMemorySize, SMEM_BYTES);
    cudaFuncSetAttribute(tc_gemm<0, 1>, cudaFuncAttributeMaxDynamicSharedMemorySize, SMEM_BYTES);
    cudaFuncSetAttribute(tc_gemm<1, 1>, cudaFuncAttributeMaxDynamicSharedMemorySize, SMEM_BYTES);

    // 0) split inputs into bf16 hi/lo
    {
        int nblk = (int)((long long)NB * LA * HD / 1024);   // 8192
        split_kernel<<<nblk, 256>>>(prem, pmH, pmL);
        split_kernel<<<nblk, 256>>>(hyp, hyH, hyL);
    }
    // 1) S = prem @ hyp^T  (A K-major [i][h], B K-major [j][h]; K=512)
    {
        dim3 grid(LB / 128, LA / 128, NB);
        tc_gemm<0, 0><<<grid, 256, SMEM_BYTES>>>(pmH, pmL, hyH, hyL, S,
                                                 HD, HD, HD, LB, sAB, sAB, sS);
    }
    // 2) row masked-softmax -> P (bf16 hi/lo, [i][j])
    {
        dim3 grid(LA, NB);
        row_softmax_kernel<<<grid, 256>>>(S, PH, PL, pmask, hmask);
    }
    // 3) column masked-softmax -> Q (bf16 hi/lo, [i][j])
    {
        dim3 grid(LB / 32, NB);
        col_softmax_kernel<<<grid, 256>>>(S, QH, QL, pmask, hmask);
    }
    // 4) AP = P @ hyp  (A K-major P [i][j], B = hyp [j][h] MN-major/trans; K=1024)
    {
        dim3 grid(HD / 128, LA / 128, NB);
        tc_gemm<0, 1><<<grid, 256, SMEM_BYTES>>>(PH, PL, hyH, hyL, AP,
                                                 LB, LB, HD, HD, sS, sAB, sAB);
    }
    // 5) AH = Q^T @ prem (A = Q [i][j] MN-major/trans (m=j,k=i),
    //                     B = prem [i][h] MN-major/trans; K=1024)
    {
        dim3 grid(HD / 128, LB / 128, NB);
        tc_gemm<1, 1><<<grid, 256, SMEM_BYTES>>>(QH, QL, pmH, pmL, AH,
                                                 LA, LA, HD, HD, sS, sAB, sAB);
    }
}

// round 8
// speedup vs baseline: 2.5445x; 1.0129x over previous
#include <cuda_runtime.h>
#include <cuda_bf16.h>
#include <cstdint>

#define NB 16
#define LA 1024
#define LB 1024
#define HD 512
#define EPSV 1e-13f

__device__ float         g_S [(long long)NB * LA * LB];
__device__ __nv_bfloat16 g_PH[(long long)NB * LA * LB];
__device__ __nv_bfloat16 g_PL[(long long)NB * LA * LB];
__device__ __nv_bfloat16 g_QH[(long long)NB * LA * LB];
__device__ __nv_bfloat16 g_QL[(long long)NB * LA * LB];
__device__ __nv_bfloat16 g_pmH[(long long)NB * LA * HD];
__device__ __nv_bfloat16 g_pmL[(long long)NB * LA * HD];
__device__ __nv_bfloat16 g_hyH[(long long)NB * LB * HD];
__device__ __nv_bfloat16 g_hyL[(long long)NB * LB * HD];

// ---------------------------------------------------------------------------
__device__ __forceinline__ uint32_t smem_u32(const void* p) {
    uint32_t a;
    asm("{ .reg .u64 t; cvta.to.shared.u64 t, %1; cvt.u32.u64 %0, t; }" : "=r"(a) : "l"(p));
    return a;
}
template <int S>
__device__ __forceinline__ uint32_t swz(uint32_t off) { return off ^ ((off >> S) & 0x70); }

__device__ __forceinline__ void cp16(uint32_t dst, const void* src) {
    asm volatile("cp.async.cg.shared.global [%0], [%1], 16;" :: "r"(dst), "l"(src));
}
__device__ __forceinline__ void cp_commit() { asm volatile("cp.async.commit_group;"); }
__device__ __forceinline__ void cp_wait0()  { asm volatile("cp.async.wait_group 0;" ::: "memory"); }

__device__ __forceinline__ void ldsm4(uint32_t* r, uint32_t addr) {
    asm volatile("ldmatrix.sync.aligned.m8n8.x4.shared.b16 {%0,%1,%2,%3}, [%4];"
                 : "=r"(r[0]), "=r"(r[1]), "=r"(r[2]), "=r"(r[3]) : "r"(addr));
}
__device__ __forceinline__ void ldsm4t(uint32_t* r, uint32_t addr) {
    asm volatile("ldmatrix.sync.aligned.m8n8.x4.trans.shared.b16 {%0,%1,%2,%3}, [%4];"
                 : "=r"(r[0]), "=r"(r[1]), "=r"(r[2]), "=r"(r[3]) : "r"(addr));
}
__device__ __forceinline__ void mma_bf16(float* c, const uint32_t* a, uint32_t b0, uint32_t b1) {
    asm volatile("mma.sync.aligned.m16n8k16.row.col.f32.bf16.bf16.f32 "
                 "{%0,%1,%2,%3}, {%4,%5,%6,%7}, {%8,%9}, {%0,%1,%2,%3};"
                 : "+f"(c[0]), "+f"(c[1]), "+f"(c[2]), "+f"(c[3])
                 : "r"(a[0]), "r"(a[1]), "r"(a[2]), "r"(a[3]), "r"(b0), "r"(b1));
}

// ---------------------------------------------------------------------------
__global__ __launch_bounds__(256)
void split_kernel(const float* __restrict__ src, __nv_bfloat16* __restrict__ oh,
                  __nv_bfloat16* __restrict__ ol)
{
    long long i = ((long long)blockIdx.x * 256 + threadIdx.x) * 4;
    float4 v = *(const float4*)(src + i);
    __nv_bfloat162 h01 = __floats2bfloat162_rn(v.x, v.y);
    __nv_bfloat162 h23 = __floats2bfloat162_rn(v.z, v.w);
    __nv_bfloat162 l01 = __floats2bfloat162_rn(v.x - __bfloat162float(h01.x),
                                               v.y - __bfloat162float(h01.y));
    __nv_bfloat162 l23 = __floats2bfloat162_rn(v.z - __bfloat162float(h23.x),
                                               v.w - __bfloat162float(h23.y));
    *(uint2*)(oh + i) = make_uint2(*(uint32_t*)&h01, *(uint32_t*)&h23);
    *(uint2*)(ol + i) = make_uint2(*(uint32_t*)&l01, *(uint32_t*)&l23);
}

// ---------------------------------------------------------------------------
// tile loaders (BK=64). MODE 0: K-major [x][k], pitch 128B, swz<3>.
// MODE 1: MN-major [k][x], pitch 2*XEXT bytes, swz<4|5>.
// ---------------------------------------------------------------------------
template <int MODE, int XEXT>
__device__ __forceinline__ void load_op(const __nv_bfloat16* __restrict__ src, int ld,
                                        int x0, int k0, uint32_t dstb, int tid) {
    if (MODE == 0) {
#pragma unroll
        for (int it = 0; it < XEXT / 32; it++) {
            int u = it * 256 + tid;
            int x = u >> 3, c = u & 7;
            cp16(dstb + swz<3>((uint32_t)(x * 128 + c * 16)),
                 src + (long long)(x0 + x) * ld + k0 + c * 8);
        }
    } else {
        constexpr int SH = (XEXT == 128) ? 4 : 5;
        constexpr int CB = (XEXT == 128) ? 4 : 5;   // log2(chunks/row)
#pragma unroll
        for (int it = 0; it < XEXT / 32; it++) {
            int u = it * 256 + tid;
            int k = u >> CB, c = u & ((1 << CB) - 1);
            cp16(dstb + swz<SH>((uint32_t)(k * (2 * XEXT) + c * 16)),
                 src + (long long)(k0 + k) * ld + x0 + c * 8);
        }
    }
}

// ---------------------------------------------------------------------------
// HMMA GEMM: C[m,n] = sum_k A[m,k]*B[n,k]; CTA tile 128x256, BK=64,
// 8 warps of 64x64, bf16 hi/lo 3-chain, 2-stage cp.async pipeline.
// ---------------------------------------------------------------------------
#define A_HALF 16384       // 128*64*2
#define B_HALF 32768       // 256*64*2
#define STAGE  (2*A_HALF + 2*B_HALF)   // 98304
#define SMEM_BYTES (2 * STAGE)         // 196608

template <int AMODE, int BMODE>
__global__ void __launch_bounds__(256, 1)
tc_gemm(const __nv_bfloat16* __restrict__ gAH, const __nv_bfloat16* __restrict__ gAL,
        const __nv_bfloat16* __restrict__ gBH, const __nv_bfloat16* __restrict__ gBL,
        float* __restrict__ gC,
        int K, int lda, int ldb, int ldc, long long sA, long long sB, long long sC)
{
    extern __shared__ char smem[];
    const uint32_t sb = smem_u32(smem);
    const int tid = threadIdx.x, wid = tid >> 5, lane = tid & 31;
    const __nv_bfloat16* pAH = gAH + (long long)blockIdx.z * sA;
    const __nv_bfloat16* pAL = gAL + (long long)blockIdx.z * sA;
    const __nv_bfloat16* pBH = gBH + (long long)blockIdx.z * sB;
    const __nv_bfloat16* pBL = gBL + (long long)blockIdx.z * sB;
    float* C = gC + (long long)blockIdx.z * sC;
    const int m0 = blockIdx.y * 128, n0 = blockIdx.x * 256;
    const int NKT = K >> 6;

    const int wm = wid >> 2;   // 0..1 (64 m-rows)
    const int wn = wid & 3;    // 0..3 (64 n-cols)
    float acc[4][8][4];
#pragma unroll
    for (int t = 0; t < 4; t++)
#pragma unroll
        for (int q = 0; q < 8; q++)
#pragma unroll
            for (int e = 0; e < 4; e++) acc[t][q][e] = 0.f;

    // prologue
    load_op<AMODE, 128>(pAH, lda, m0, 0, sb + 0,            tid);
    load_op<AMODE, 128>(pAL, lda, m0, 0, sb + A_HALF,       tid);
    load_op<BMODE, 256>(pBH, ldb, n0, 0, sb + 2 * A_HALF,   tid);
    load_op<BMODE, 256>(pBL, ldb, n0, 0, sb + 2 * A_HALF + B_HALF, tid);
    cp_commit();

    int buf = 0;
    for (int kt = 0; kt < NKT; kt++) {
        cp_wait0();
        __syncthreads();
        if (kt + 1 < NKT) {
            uint32_t nb = sb + (uint32_t)(buf ^ 1) * STAGE;
            int k0 = (kt + 1) * 64;
            load_op<AMODE, 128>(pAH, lda, m0, k0, nb + 0,            tid);
            load_op<AMODE, 128>(pAL, lda, m0, k0, nb + A_HALF,       tid);
            load_op<BMODE, 256>(pBH, ldb, n0, k0, nb + 2 * A_HALF,   tid);
            load_op<BMODE, 256>(pBL, ldb, n0, k0, nb + 2 * A_HALF + B_HALF, tid);
            cp_commit();
        }
        const uint32_t tb = sb + (uint32_t)buf * STAGE;
        const uint32_t sAh = tb, sAl = tb + A_HALF;
        const uint32_t sBh = tb + 2 * A_HALF, sBl = tb + 2 * A_HALF + B_HALF;
#pragma unroll
        for (int ks = 0; ks < 4; ks++) {
            uint32_t a_hi[4][4], a_lo[4][4];
#pragma unroll
            for (int t = 0; t < 4; t++) {
                if (AMODE == 0) {
                    uint32_t off = (uint32_t)((wm * 64 + t * 16 + (lane & 15)) * 128
                                              + ks * 32 + (lane >> 4) * 16);
                    uint32_t sw = swz<3>(off);
                    ldsm4(a_hi[t], sAh + sw);
                    ldsm4(a_lo[t], sAl + sw);
                } else {
                    uint32_t off = (uint32_t)((ks * 16 + (lane & 7) + ((lane >> 4) & 1) * 8) * 256
                                              + (wm * 64 + t * 16 + ((lane >> 3) & 1) * 8) * 2);
                    uint32_t sw = swz<4>(off);
                    ldsm4t(a_hi[t], sAh + sw);
                    ldsm4t(a_lo[t], sAl + sw);
                }
            }
#pragma unroll
            for (int p = 0; p < 4; p++) {
                uint32_t b_hi[4], b_lo[4];
                if (BMODE == 0) {
                    uint32_t off = (uint32_t)((wn * 64 + p * 16 + (lane & 7) + ((lane >> 4) << 3)) * 128
                                              + ks * 32 + ((lane >> 3) & 1) * 16);
                    uint32_t sw = swz<3>(off);
                    ldsm4(b_hi, sBh + sw);
                    ldsm4(b_lo, sBl + sw);
                } else {
                    uint32_t off = (uint32_t)((ks * 16 + (lane & 15)) * 512
                                              + (wn * 64 + p * 16 + (lane >> 4) * 8) * 2);
                    uint32_t sw = swz<5>(off);
                    ldsm4t(b_hi, sBh + sw);
                    ldsm4t(b_lo, sBl + sw);
                }
#pragma unroll
                for (int t = 0; t < 4; t++)
#pragma unroll
                    for (int qq = 0; qq < 2; qq++) {
                        const int q = p * 2 + qq, h = qq * 2;
                        mma_bf16(acc[t][q], a_hi[t], b_hi[h], b_hi[h + 1]);
                        mma_bf16(acc[t][q], a_hi[t], b_lo[h], b_lo[h + 1]);
                        mma_bf16(acc[t][q], a_lo[t], b_hi[h], b_hi[h + 1]);
                    }
            }
        }
        buf ^= 1;
        __syncthreads();
    }

    // epilogue
    const int row0 = lane >> 2, col0 = (lane & 3) * 2;
#pragma unroll
    for (int t = 0; t < 4; t++) {
        const int r = m0 + wm * 64 + t * 16 + row0;
#pragma unroll
        for (int q = 0; q < 8; q++) {
            const int c = n0 + wn * 64 + q * 8 + col0;
            *(float2*)&C[(long long)r * ldc + c] = make_float2(acc[t][q][0], acc[t][q][1]);
            *(float2*)&C[(long long)(r + 8) * ldc + c] = make_float2(acc[t][q][2], acc[t][q][3]);
        }
    }
}

// ---------------------------------------------------------------------------
// Row-direction masked softmax -> bf16 hi/lo
// ---------------------------------------------------------------------------
__global__ __launch_bounds__(256)
void row_softmax_kernel(const float* __restrict__ S,
                        __nv_bfloat16* __restrict__ PH, __nv_bfloat16* __restrict__ PL,
                        const float* __restrict__ pmask, const float* __restrict__ hmask)
{
    const int i = blockIdx.x;
    const int b = blockIdx.y;
    const long long rowoff = ((long long)b * LA + i) * LB;
    const int tid = threadIdx.x;

    float4 s = *(const float4*)&S[rowoff + tid * 4];
    float4 h = *(const float4*)&hmask[(long long)b * LB + tid * 4];
    float l0 = s.x * h.x, l1 = s.y * h.y, l2 = s.z * h.z, l3 = s.w * h.w;

    __shared__ float redA[8], redB[8];

    float v = fmaxf(fmaxf(l0, l1), fmaxf(l2, l3));
#pragma unroll
    for (int o = 16; o; o >>= 1) v = fmaxf(v, __shfl_xor_sync(0xffffffffu, v, o));
    if ((tid & 31) == 0) redA[tid >> 5] = v;
    __syncthreads();
    float m = redA[0];
#pragma unroll
    for (int w = 1; w < 8; w++) m = fmaxf(m, redA[w]);
    __syncthreads();

    float e0 = __expf(l0 - m), e1 = __expf(l1 - m), e2 = __expf(l2 - m), e3 = __expf(l3 - m);
    float d = e0 + e1 + e2 + e3;
    float e = h.x * e0 + h.y * e1 + h.z * e2 + h.w * e3;
#pragma unroll
    for (int o = 16; o; o >>= 1) {
        d += __shfl_xor_sync(0xffffffffu, d, o);
        e += __shfl_xor_sync(0xffffffffu, e, o);
    }
    if ((tid & 31) == 0) { redA[tid >> 5] = d; redB[tid >> 5] = e; }
    __syncthreads();
    float D = 0.f, E = 0.f;
#pragma unroll
    for (int w = 0; w < 8; w++) { D += redA[w]; E += redB[w]; }

    const float pm = pmask[(long long)b * LA + i];
    const float scale = pm / (E + EPSV * D);

    float v0 = h.x * e0 * scale, v1 = h.y * e1 * scale;
    float v2 = h.z * e2 * scale, v3 = h.w * e3 * scale;
    __nv_bfloat162 h01 = __floats2bfloat162_rn(v0, v1);
    __nv_bfloat162 h23 = __floats2bfloat162_rn(v2, v3);
    __nv_bfloat162 q01 = __floats2bfloat162_rn(v0 - __bfloat162float(h01.x),
                                               v1 - __bfloat162float(h01.y));
    __nv_bfloat162 q23 = __floats2bfloat162_rn(v2 - __bfloat162float(h23.x),
                                               v3 - __bfloat162float(h23.y));
    *(uint2*)&PH[rowoff + tid * 4] = make_uint2(*(uint32_t*)&h01, *(uint32_t*)&h23);
    *(uint2*)&PL[rowoff + tid * 4] = make_uint2(*(uint32_t*)&q01, *(uint32_t*)&q23);
}

// ---------------------------------------------------------------------------
// Column-direction masked softmax, online (2 passes over S) -> bf16 hi/lo
// ---------------------------------------------------------------------------
__global__ __launch_bounds__(256)
void col_softmax_kernel(const float* __restrict__ S,
                        __nv_bfloat16* __restrict__ QH, __nv_bfloat16* __restrict__ QL,
                        const float* __restrict__ pmask, const float* __restrict__ hmask)
{
    const int b = blockIdx.y;
    const int tx = threadIdx.x & 31;
    const int ty = threadIdx.x >> 5;
    const int j = blockIdx.x * 32 + tx;
    const float* Sb = S + (long long)b * LA * LB;
    __nv_bfloat16* Qh = QH + (long long)b * LA * LB;
    __nv_bfloat16* Ql = QL + (long long)b * LA * LB;
    const float* pm = pmask + (long long)b * LA;

    __shared__ float redM[8][32], redD[8][32], redE[8][32];

    // pass 1: online max + sums
    float m = -1e30f, D = 0.f, E = 0.f;
    for (int r = ty; r < LA; r += 8) {
        float pmr = pm[r];
        float l = Sb[(long long)r * LB + j] * pmr;
        if (l <= m) {
            float ev = __expf(l - m);
            D += ev; E += pmr * ev;
        } else {
            float f = __expf(m - l);
            D = D * f + 1.f;
            E = E * f + pmr;
            m = l;
        }
    }
    redM[ty][tx] = m; redD[ty][tx] = D; redE[ty][tx] = E;
    __syncthreads();
    float M = redM[0][tx];
#pragma unroll
    for (int t = 1; t < 8; t++) M = fmaxf(M, redM[t][tx]);
    float Dt = 0.f, Et = 0.f;
#pragma unroll
    for (int t = 0; t < 8; t++) {
        float f = __expf(redM[t][tx] - M);
        Dt += redD[t][tx] * f;
        Et += redE[t][tx] * f;
    }

    const float scale = hmask[(long long)b * LB + j] / (Et + EPSV * Dt);

    // pass 2: write
    for (int r = ty; r < LA; r += 8) {
        float pmr = pm[r];
        float ev = __expf(Sb[(long long)r * LB + j] * pmr - M);
        float val = pmr * ev * scale;
        __nv_bfloat16 hh = __float2bfloat16_rn(val);
        __nv_bfloat16 ll = __float2bfloat16_rn(val - __bfloat162float(hh));
        Qh[(long long)r * LB + j] = hh;
        Ql[(long long)r * LB + j] = ll;
    }
}

// ---------------------------------------------------------------------------
extern "C" void kernel_launch(void* const* d_in, const int* in_sizes, int n_in,
                              void* d_out, int out_size)
{
    const float* prem  = (const float*)d_in[0];
    const float* pmask = (const float*)d_in[1];
    const float* hyp   = (const float*)d_in[2];
    const float* hmask = (const float*)d_in[3];

    float* AP  = (float*)d_out;
    float* AHo = AP + (long long)NB * LA * HD;

    void *pS, *pPH, *pPL, *pQH, *pQL, *ppmH, *ppmL, *phyH, *phyL;
    cudaGetSymbolAddress(&pS, g_S);
    cudaGetSymbolAddress(&pPH, g_PH);  cudaGetSymbolAddress(&pPL, g_PL);
    cudaGetSymbolAddress(&pQH, g_QH);  cudaGetSymbolAddress(&pQL, g_QL);
    cudaGetSymbolAddress(&ppmH, g_pmH); cudaGetSymbolAddress(&ppmL, g_pmL);
    cudaGetSymbolAddress(&phyH, g_hyH); cudaGetSymbolAddress(&phyL, g_hyL);
    float* S = (float*)pS;
    __nv_bfloat16 *PH = (__nv_bfloat16*)pPH, *PL = (__nv_bfloat16*)pPL;
    __nv_bfloat16 *QH = (__nv_bfloat16*)pQH, *QL = (__nv_bfloat16*)pQL;
    __nv_bfloat16 *pmH = (__nv_bfloat16*)ppmH, *pmL = (__nv_bfloat16*)ppmL;
    __nv_bfloat16 *hyH = (__nv_bfloat16*)phyH, *hyL = (__nv_bfloat16*)phyL;

    const long long sAB = (long long)LA * HD;
    const long long sS  = (long long)LA * LB;

    cudaFuncSetAttribute(tc_gemm<0, 0>, cudaFuncAttributeMaxDynamicSharedMemorySize, SMEM_BYTES);
    cudaFuncSetAttribute(tc_gemm<0, 1>, cudaFuncAttributeMaxDynamicSharedMemorySize, SMEM_BYTES);
    cudaFuncSetAttribute(tc_gemm<1, 1>, cudaFuncAttributeMaxDynamicSharedMemorySize, SMEM_BYTES);

    // 0) split inputs
    {
        int nblk = (int)((long long)NB * LA * HD / 1024);
        split_kernel<<<nblk, 256>>>(prem, pmH, pmL);
        split_kernel<<<nblk, 256>>>(hyp, hyH, hyL);
    }
    // 1) S = prem @ hyp^T  (K=512, A/B K-major)
    {
        dim3 grid(LB / 256, LA / 128, NB);
        tc_gemm<0, 0><<<grid, 256, SMEM_BYTES>>>(pmH, pmL, hyH, hyL, S,
                                                 HD, HD, HD, LB, sAB, sAB, sS);
    }
    // 2) row masked-softmax -> P
    {
        dim3 grid(LA, NB);
        row_softmax_kernel<<<grid, 256>>>(S, PH, PL, pmask, hmask);
    }
    // 3) column masked-softmax -> Q
    {
        dim3 grid(LB / 32, NB);
        col_softmax_kernel<<<grid, 256>>>(S, QH, QL, pmask, hmask);
    }
    // 4) AP = P @ hyp  (A K-major, B MN-major/trans; K=1024)
    {
        dim3 grid(HD / 256, LA / 128, NB);
        tc_gemm<0, 1><<<grid, 256, SMEM_BYTES>>>(PH, PL, hyH, hyL, AP,
                                                 LB, LB, HD, HD, sS, sAB, sAB);
    }
    // 5) AH = Q^T @ prem  (A MN-major/trans, B MN-major/trans; K=1024)
    {
        dim3 grid(HD / 256, LB / 128, NB);
        tc_gemm<1, 1><<<grid, 256, SMEM_BYTES>>>(QH, QL, pmH, pmL, AHo,
                                                 LA, LB, HD, HD, sS, sAB, sAB);
    }
}

// round 12
// speedup vs baseline: 2.8836x; 1.1333x over previous
#include <cuda_runtime.h>
#include <cuda_bf16.h>
#include <cstdint>

#define NB 16
#define LA 1024
#define LB 1024
#define HD 512
#define EPSV 1e-13f

__device__ float         g_S [(long long)NB * LA * LB];
__device__ __nv_bfloat16 g_PH[(long long)NB * LA * LB];
__device__ __nv_bfloat16 g_PL[(long long)NB * LA * LB];
__device__ __nv_bfloat16 g_QH[(long long)NB * LA * LB];
__device__ __nv_bfloat16 g_QL[(long long)NB * LA * LB];
__device__ __nv_bfloat16 g_pmH[(long long)NB * LA * HD];
__device__ __nv_bfloat16 g_pmL[(long long)NB * LA * HD];
__device__ __nv_bfloat16 g_hyH[(long long)NB * LB * HD];
__device__ __nv_bfloat16 g_hyL[(long long)NB * LB * HD];

// ---------------------------------------------------------------------------
__device__ __forceinline__ uint32_t smem_u32(const void* p) {
    uint32_t a;
    asm("{ .reg .u64 t; cvta.to.shared.u64 t, %1; cvt.u32.u64 %0, t; }" : "=r"(a) : "l"(p));
    return a;
}
// 256B-pitch swizzle (MN-major tiles)
__device__ __forceinline__ uint32_t swzMN(uint32_t off) { return off ^ ((off >> 4) & 0x70); }
// 64B-pitch swizzle (K-major BK=32): XOR chunk bits[4:5] with row-pair index.
__device__ __forceinline__ uint32_t swzK(uint32_t off) { return off ^ (((off >> 7) & 0x3) << 4); }

__device__ __forceinline__ void cp16(uint32_t dst, const void* src) {
    asm volatile("cp.async.cg.shared.global [%0], [%1], 16;" :: "r"(dst), "l"(src));
}
__device__ __forceinline__ void cp_commit() { asm volatile("cp.async.commit_group;"); }
__device__ __forceinline__ void cp_wait1()  { asm volatile("cp.async.wait_group 1;" ::: "memory"); }

__device__ __forceinline__ void ldsm4(uint32_t* r, uint32_t addr) {
    asm volatile("ldmatrix.sync.aligned.m8n8.x4.shared.b16 {%0,%1,%2,%3}, [%4];"
                 : "=r"(r[0]), "=r"(r[1]), "=r"(r[2]), "=r"(r[3]) : "r"(addr));
}
__device__ __forceinline__ void ldsm4t(uint32_t* r, uint32_t addr) {
    asm volatile("ldmatrix.sync.aligned.m8n8.x4.trans.shared.b16 {%0,%1,%2,%3}, [%4];"
                 : "=r"(r[0]), "=r"(r[1]), "=r"(r[2]), "=r"(r[3]) : "r"(addr));
}
__device__ __forceinline__ void mma_bf16(float* c, const uint32_t* a, uint32_t b0, uint32_t b1) {
    asm volatile("mma.sync.aligned.m16n8k16.row.col.f32.bf16.bf16.f32 "
                 "{%0,%1,%2,%3}, {%4,%5,%6,%7}, {%8,%9}, {%0,%1,%2,%3};"
                 : "+f"(c[0]), "+f"(c[1]), "+f"(c[2]), "+f"(c[3])
                 : "r"(a[0]), "r"(a[1]), "r"(a[2]), "r"(a[3]), "r"(b0), "r"(b1));
}

// ---------------------------------------------------------------------------
__global__ __launch_bounds__(256)
void split_kernel(const float* __restrict__ src, __nv_bfloat16* __restrict__ oh,
                  __nv_bfloat16* __restrict__ ol)
{
    long long i = ((long long)blockIdx.x * 256 + threadIdx.x) * 4;
    float4 v = *(const float4*)(src + i);
    __nv_bfloat162 h01 = __floats2bfloat162_rn(v.x, v.y);
    __nv_bfloat162 h23 = __floats2bfloat162_rn(v.z, v.w);
    __nv_bfloat162 l01 = __floats2bfloat162_rn(v.x - __bfloat162float(h01.x),
                                               v.y - __bfloat162float(h01.y));
    __nv_bfloat162 l23 = __floats2bfloat162_rn(v.z - __bfloat162float(h23.x),
                                               v.w - __bfloat162float(h23.y));
    *(uint2*)(oh + i) = make_uint2(*(uint32_t*)&h01, *(uint32_t*)&h23);
    *(uint2*)(ol + i) = make_uint2(*(uint32_t*)&l01, *(uint32_t*)&l23);
}

// ---------------------------------------------------------------------------
// tile loaders, BK=32. MODE 0: K-major [128][32], 64B pitch, swzK (8 KB).
// MODE 1: MN-major [32][128], 256B pitch, swzMN (8 KB).
// ---------------------------------------------------------------------------
__device__ __forceinline__ void load_opK(const __nv_bfloat16* __restrict__ src, int ld,
                                         int x0, int k0, uint32_t dstb, int tid) {
#pragma unroll
    for (int it = 0; it < 2; it++) {
        int u = it * 256 + tid;
        int x = u >> 2, c = u & 3;
        cp16(dstb + swzK((uint32_t)(x * 64 + c * 16)),
             src + (long long)(x0 + x) * ld + k0 + c * 8);
    }
}
__device__ __forceinline__ void load_opMN(const __nv_bfloat16* __restrict__ src, int ld,
                                          int x0, int k0, uint32_t dstb, int tid) {
#pragma unroll
    for (int it = 0; it < 2; it++) {
        int u = it * 256 + tid;
        int k = u >> 4, c = u & 15;
        cp16(dstb + swzMN((uint32_t)(k * 256 + c * 16)),
             src + (long long)(k0 + k) * ld + x0 + c * 8);
    }
}

#define OPQ   8192
#define STAGE (4 * OPQ)             // 32 KB
#define SMEM_BYTES (3 * STAGE)      // 96 KB -> 2 CTAs/SM

// ---------------------------------------------------------------------------
// GEMM mainloop body (shared by both kernels). amode: 0 K-major A, 1 MN-major A.
// bmode likewise for B. amode/bmode uniform per CTA.
// ---------------------------------------------------------------------------
__device__ __forceinline__ void gemm_body(
    const __nv_bfloat16* pAH, const __nv_bfloat16* pAL,
    const __nv_bfloat16* pBH, const __nv_bfloat16* pBL,
    float* C, int K, int lda, int ldb, int ldc,
    int m0, int n0, int amode, int bmode,
    uint32_t sb, int tid, int wid, int lane)
{
    const int wm = wid >> 1;   // 0..3 (32 m-rows)
    const int wn = wid & 1;    // 0..1 (64 n-cols)
    const int NKT = K >> 5;

    float acc[2][8][4];
#pragma unroll
    for (int t = 0; t < 2; t++)
#pragma unroll
        for (int q = 0; q < 8; q++)
#pragma unroll
            for (int e = 0; e < 4; e++) acc[t][q][e] = 0.f;

    auto load_stage = [&](int kt, int st) {
        uint32_t nb = sb + (uint32_t)st * STAGE;
        int k0 = kt * 32;
        if (amode == 0) {
            load_opK(pAH, lda, m0, k0, nb + 0 * OPQ, tid);
            load_opK(pAL, lda, m0, k0, nb + 1 * OPQ, tid);
        } else {
            load_opMN(pAH, lda, m0, k0, nb + 0 * OPQ, tid);
            load_opMN(pAL, lda, m0, k0, nb + 1 * OPQ, tid);
        }
        if (bmode == 0) {
            load_opK(pBH, ldb, n0, k0, nb + 2 * OPQ, tid);
            load_opK(pBL, ldb, n0, k0, nb + 3 * OPQ, tid);
        } else {
            load_opMN(pBH, ldb, n0, k0, nb + 2 * OPQ, tid);
            load_opMN(pBL, ldb, n0, k0, nb + 3 * OPQ, tid);
        }
        cp_commit();
    };

    load_stage(0, 0);
    load_stage(1, 1);

    int st = 0;
    for (int kt = 0; kt < NKT; kt++) {
        cp_wait1();
        __syncthreads();
        if (kt + 2 < NKT) load_stage(kt + 2, (st + 2) % 3);

        const uint32_t tb = sb + (uint32_t)st * STAGE;
        const uint32_t sAh = tb, sAl = tb + OPQ, sBh = tb + 2 * OPQ, sBl = tb + 3 * OPQ;
#pragma unroll
        for (int ks = 0; ks < 2; ks++) {
            uint32_t a_hi[2][4], a_lo[2][4];
#pragma unroll
            for (int t = 0; t < 2; t++) {
                if (amode == 0) {
                    uint32_t off = (uint32_t)((wm * 32 + t * 16 + (lane & 15)) * 64
                                              + ks * 32 + (lane >> 4) * 16);
                    uint32_t sw = swzK(off);
                    ldsm4(a_hi[t], sAh + sw);
                    ldsm4(a_lo[t], sAl + sw);
                } else {
                    uint32_t off = (uint32_t)((ks * 16 + (lane & 7) + ((lane >> 4) & 1) * 8) * 256
                                              + (wm * 32 + t * 16 + ((lane >> 3) & 1) * 8) * 2);
                    uint32_t sw = swzMN(off);
                    ldsm4t(a_hi[t], sAh + sw);
                    ldsm4t(a_lo[t], sAl + sw);
                }
            }
#pragma unroll
            for (int p = 0; p < 4; p++) {
                uint32_t b_hi[4], b_lo[4];
                if (bmode == 0) {
                    uint32_t off = (uint32_t)((wn * 64 + p * 16 + (lane & 7) + ((lane >> 4) << 3)) * 64
                                              + ks * 32 + ((lane >> 3) & 1) * 16);
                    uint32_t sw = swzK(off);
                    ldsm4(b_hi, sBh + sw);
                    ldsm4(b_lo, sBl + sw);
                } else {
                    uint32_t off = (uint32_t)((ks * 16 + (lane & 15)) * 256
                                              + (wn * 64 + p * 16 + (lane >> 4) * 8) * 2);
                    uint32_t sw = swzMN(off);
                    ldsm4t(b_hi, sBh + sw);
                    ldsm4t(b_lo, sBl + sw);
                }
#pragma unroll
                for (int t = 0; t < 2; t++)
#pragma unroll
                    for (int qq = 0; qq < 2; qq++) {
                        const int q = p * 2 + qq, h = qq * 2;
                        mma_bf16(acc[t][q], a_hi[t], b_hi[h], b_hi[h + 1]);
                        mma_bf16(acc[t][q], a_hi[t], b_lo[h], b_lo[h + 1]);
                        mma_bf16(acc[t][q], a_lo[t], b_hi[h], b_hi[h + 1]);
                    }
            }
        }
        st = (st + 1) % 3;
    }

    const int row0 = lane >> 2, col0 = (lane & 3) * 2;
#pragma unroll
    for (int t = 0; t < 2; t++) {
        const int r = m0 + wm * 32 + t * 16 + row0;
#pragma unroll
        for (int q = 0; q < 8; q++) {
            const int c = n0 + wn * 64 + q * 8 + col0;
            *(float2*)&C[(long long)r * ldc + c] = make_float2(acc[t][q][0], acc[t][q][1]);
            *(float2*)&C[(long long)(r + 8) * ldc + c] = make_float2(acc[t][q][2], acc[t][q][3]);
        }
    }
}

// ---------------------------------------------------------------------------
// GEMM1: S = prem @ hyp^T (both K-major), K=512
// ---------------------------------------------------------------------------
__global__ void __launch_bounds__(256, 2)
gemm1_kernel(const __nv_bfloat16* __restrict__ AHp, const __nv_bfloat16* __restrict__ ALp,
             const __nv_bfloat16* __restrict__ BHp, const __nv_bfloat16* __restrict__ BLp,
             float* __restrict__ Sp)
{
    extern __shared__ char smem[];
    const uint32_t sb = smem_u32(smem);
    const int tid = threadIdx.x, wid = tid >> 5, lane = tid & 31;
    const long long b = blockIdx.z;
    gemm_body(AHp + b * (LA * HD), ALp + b * (LA * HD),
              BHp + b * (LB * HD), BLp + b * (LB * HD),
              (float*)(Sp + b * (LA * LB)),
              HD, HD, HD, LB,
              blockIdx.y * 128, blockIdx.x * 128, 0, 0, sb, tid, wid, lane);
}

// ---------------------------------------------------------------------------
// Fused GEMM2+GEMM3: grid.z 0..NB-1 -> AP = P @ hyp (A K-major, B MN-major);
//                    grid.z NB..2NB-1 -> AH = Q^T @ prem (A MN-major, B MN-major).
// Both K = 1024.
// ---------------------------------------------------------------------------
__global__ void __launch_bounds__(256, 2)
gemm23_kernel(const __nv_bfloat16* __restrict__ PHp, const __nv_bfloat16* __restrict__ PLp,
              const __nv_bfloat16* __restrict__ QHp, const __nv_bfloat16* __restrict__ QLp,
              const __nv_bfloat16* __restrict__ hyHp, const __nv_bfloat16* __restrict__ hyLp,
              const __nv_bfloat16* __restrict__ pmHp, const __nv_bfloat16* __restrict__ pmLp,
              float* __restrict__ APp, float* __restrict__ AHp)
{
    extern __shared__ char smem[];
    const uint32_t sb = smem_u32(smem);
    const int tid = threadIdx.x, wid = tid >> 5, lane = tid & 31;
    const int z = blockIdx.z;
    if (z < NB) {
        const long long b = z;
        gemm_body(PHp + b * (LA * LB), PLp + b * (LA * LB),
                  hyHp + b * (LB * HD), hyLp + b * (LB * HD),
                  APp + b * (LA * HD),
                  LB, LB, HD, HD,
                  blockIdx.y * 128, blockIdx.x * 128, 0, 1, sb, tid, wid, lane);
    } else {
        const long long b = z - NB;
        gemm_body(QHp + b * (LA * LB), QLp + b * (LA * LB),
                  pmHp + b * (LA * HD), pmLp + b * (LA * HD),
                  AHp + b * (LB * HD),
                  LA, LB, HD, HD,
                  blockIdx.y * 128, blockIdx.x * 128, 1, 1, sb, tid, wid, lane);
    }
}

// ---------------------------------------------------------------------------
// Fused softmax: blockIdx.x < LA -> row-softmax block (i = blockIdx.x);
//                else            -> col-softmax block (32 cols, jb = x - LA).
// ---------------------------------------------------------------------------
__global__ __launch_bounds__(256)
void softmax_kernel(const float* __restrict__ S,
                    __nv_bfloat16* __restrict__ PH, __nv_bfloat16* __restrict__ PL,
                    __nv_bfloat16* __restrict__ QH, __nv_bfloat16* __restrict__ QL,
                    const float* __restrict__ pmask, const float* __restrict__ hmask)
{
    const int b = blockIdx.y;
    const int tid = threadIdx.x;
    __shared__ float shm[3][8][32];

    if (blockIdx.x < LA) {
        // ---- row softmax ----
        const int i = blockIdx.x;
        const long long rowoff = ((long long)b * LA + i) * LB;

        float4 s = *(const float4*)&S[rowoff + tid * 4];
        float4 h = *(const float4*)&hmask[(long long)b * LB + tid * 4];
        float l0 = s.x * h.x, l1 = s.y * h.y, l2 = s.z * h.z, l3 = s.w * h.w;

        float v = fmaxf(fmaxf(l0, l1), fmaxf(l2, l3));
#pragma unroll
        for (int o = 16; o; o >>= 1) v = fmaxf(v, __shfl_xor_sync(0xffffffffu, v, o));
        if ((tid & 31) == 0) shm[0][0][tid >> 5] = v;
        __syncthreads();
        float m = shm[0][0][0];
#pragma unroll
        for (int w = 1; w < 8; w++) m = fmaxf(m, shm[0][0][w]);
        __syncthreads();

        float e0 = __expf(l0 - m), e1 = __expf(l1 - m), e2 = __expf(l2 - m), e3 = __expf(l3 - m);
        float d = e0 + e1 + e2 + e3;
        float e = h.x * e0 + h.y * e1 + h.z * e2 + h.w * e3;
#pragma unroll
        for (int o = 16; o; o >>= 1) {
            d += __shfl_xor_sync(0xffffffffu, d, o);
            e += __shfl_xor_sync(0xffffffffu, e, o);
        }
        if ((tid & 31) == 0) { shm[0][0][tid >> 5] = d; shm[0][1][tid >> 5] = e; }
        __syncthreads();
        float D = 0.f, E = 0.f;
#pragma unroll
        for (int w = 0; w < 8; w++) { D += shm[0][0][w]; E += shm[0][1][w]; }

        const float pm = pmask[(long long)b * LA + i];
        const float scale = pm / (E + EPSV * D);

        float v0 = h.x * e0 * scale, v1 = h.y * e1 * scale;
        float v2 = h.z * e2 * scale, v3 = h.w * e3 * scale;
        __nv_bfloat162 h01 = __floats2bfloat162_rn(v0, v1);
        __nv_bfloat162 h23 = __floats2bfloat162_rn(v2, v3);
        __nv_bfloat162 q01 = __floats2bfloat162_rn(v0 - __bfloat162float(h01.x),
                                                   v1 - __bfloat162float(h01.y));
        __nv_bfloat162 q23 = __floats2bfloat162_rn(v2 - __bfloat162float(h23.x),
                                                   v3 - __bfloat162float(h23.y));
        *(uint2*)&PH[rowoff + tid * 4] = make_uint2(*(uint32_t*)&h01, *(uint32_t*)&h23);
        *(uint2*)&PL[rowoff + tid * 4] = make_uint2(*(uint32_t*)&q01, *(uint32_t*)&q23);
    } else {
        // ---- col softmax (online) ----
        const int tx = tid & 31, ty = tid >> 5;
        const int j = (blockIdx.x - LA) * 32 + tx;
        const float* Sb = S + (long long)b * LA * LB;
        __nv_bfloat16* Qh = QH + (long long)b * LA * LB;
        __nv_bfloat16* Ql = QL + (long long)b * LA * LB;
        const float* pm = pmask + (long long)b * LA;

        float m = -1e30f, D = 0.f, E = 0.f;
        for (int r = ty; r < LA; r += 8) {
            float pmr = pm[r];
            float l = Sb[(long long)r * LB + j] * pmr;
            if (l <= m) {
                float ev = __expf(l - m);
                D += ev; E += pmr * ev;
            } else {
                float f = __expf(m - l);
                D = D * f + 1.f;
                E = E * f + pmr;
                m = l;
            }
        }
        shm[0][ty][tx] = m; shm[1][ty][tx] = D; shm[2][ty][tx] = E;
        __syncthreads();
        float M = shm[0][0][tx];
#pragma unroll
        for (int t = 1; t < 8; t++) M = fmaxf(M, shm[0][t][tx]);
        float Dt = 0.f, Et = 0.f;
#pragma unroll
        for (int t = 0; t < 8; t++) {
            float f = __expf(shm[0][t][tx] - M);
            Dt += shm[1][t][tx] * f;
            Et += shm[2][t][tx] * f;
        }

        const float scale = hmask[(long long)b * LB + j] / (Et + EPSV * Dt);

        for (int r = ty; r < LA; r += 8) {
            float pmr = pm[r];
            float ev = __expf(Sb[(long long)r * LB + j] * pmr - M);
            float val = pmr * ev * scale;
            __nv_bfloat16 hh = __float2bfloat16_rn(val);
            __nv_bfloat16 ll = __float2bfloat16_rn(val - __bfloat162float(hh));
            Qh[(long long)r * LB + j] = hh;
            Ql[(long long)r * LB + j] = ll;
        }
    }
}

// ---------------------------------------------------------------------------
extern "C" void kernel_launch(void* const* d_in, const int* in_sizes, int n_in,
                              void* d_out, int out_size)
{
    const float* prem  = (const float*)d_in[0];
    const float* pmask = (const float*)d_in[1];
    const float* hyp   = (const float*)d_in[2];
    const float* hmask = (const float*)d_in[3];

    float* AP  = (float*)d_out;
    float* AHo = AP + (long long)NB * LA * HD;

    void *pS, *pPH, *pPL, *pQH, *pQL, *ppmH, *ppmL, *phyH, *phyL;
    cudaGetSymbolAddress(&pS, g_S);
    cudaGetSymbolAddress(&pPH, g_PH);  cudaGetSymbolAddress(&pPL, g_PL);
    cudaGetSymbolAddress(&pQH, g_QH);  cudaGetSymbolAddress(&pQL, g_QL);
    cudaGetSymbolAddress(&ppmH, g_pmH); cudaGetSymbolAddress(&ppmL, g_pmL);
    cudaGetSymbolAddress(&phyH, g_hyH); cudaGetSymbolAddress(&phyL, g_hyL);
    float* S = (float*)pS;
    __nv_bfloat16 *PH = (__nv_bfloat16*)pPH, *PL = (__nv_bfloat16*)pPL;
    __nv_bfloat16 *QH = (__nv_bfloat16*)pQH, *QL = (__nv_bfloat16*)pQL;
    __nv_bfloat16 *pmH = (__nv_bfloat16*)ppmH, *pmL = (__nv_bfloat16*)ppmL;
    __nv_bfloat16 *hyH = (__nv_bfloat16*)phyH, *hyL = (__nv_bfloat16*)phyL;

    cudaFuncSetAttribute(gemm1_kernel,  cudaFuncAttributeMaxDynamicSharedMemorySize, SMEM_BYTES);
    cudaFuncSetAttribute(gemm23_kernel, cudaFuncAttributeMaxDynamicSharedMemorySize, SMEM_BYTES);

    // 0) split inputs into bf16 hi/lo
    {
        int nblk = (int)((long long)NB * LA * HD / 1024);
        split_kernel<<<nblk, 256>>>(prem, pmH, pmL);
        split_kernel<<<nblk, 256>>>(hyp, hyH, hyL);
    }
    // 1) S = prem @ hyp^T  (K=512)
    {
        dim3 grid(LB / 128, LA / 128, NB);
        gemm1_kernel<<<grid, 256, SMEM_BYTES>>>(pmH, pmL, hyH, hyL, S);
    }
    // 2) fused row+col masked softmax -> P (bf16 hi/lo) and Q (bf16 hi/lo)
    {
        dim3 grid(LA + LB / 32, NB);
        softmax_kernel<<<grid, 256>>>(S, PH, PL, QH, QL, pmask, hmask);
    }
    // 3) fused GEMM2+GEMM3 -> AP and AH   (K=1024 each, 1024 CTAs total)
    {
        dim3 grid(HD / 128, LA / 128, 2 * NB);
        gemm23_kernel<<<grid, 256, SMEM_BYTES>>>(PH, PL, QH, QL,
                                                 hyH, hyL, pmH, pmL, AP, AHo);
    }
}

// round 14
// speedup vs baseline: 3.3922x; 1.1764x over previous
#include <cuda_runtime.h>
#include <cuda_fp16.h>
#include <cstdint>

#define NB 16
#define LA 1024
#define LB 1024
#define HD 512
#define EPSV 1e-13f

__device__ float  g_S [(long long)NB * LA * LB];
__device__ __half g_P [(long long)NB * LA * LB];    // row-softmax out (fp16, single)
__device__ __half g_QH[(long long)NB * LA * LB];    // col-softmax out hi
__device__ __half g_QL[(long long)NB * LA * LB];    // col-softmax out lo
__device__ __half g_pmH[(long long)NB * LA * HD];   // prem hi
__device__ __half g_pmL[(long long)NB * LA * HD];   // prem lo
__device__ __half g_hyH[(long long)NB * LB * HD];   // hyp hi
__device__ __half g_hyL[(long long)NB * LB * HD];   // hyp lo

// ---------------------------------------------------------------------------
__device__ __forceinline__ uint32_t smem_u32(const void* p) {
    uint32_t a;
    asm("{ .reg .u64 t; cvta.to.shared.u64 t, %1; cvt.u32.u64 %0, t; }" : "=r"(a) : "l"(p));
    return a;
}
// 256B-pitch swizzle (MN-major tiles)
__device__ __forceinline__ uint32_t swzMN(uint32_t off) { return off ^ ((off >> 4) & 0x70); }
// 64B-pitch swizzle (K-major BK=32): XOR chunk bits[4:5] with row-pair index.
__device__ __forceinline__ uint32_t swzK(uint32_t off) { return off ^ (((off >> 7) & 0x3) << 4); }

__device__ __forceinline__ void cp16(uint32_t dst, const void* src) {
    asm volatile("cp.async.cg.shared.global [%0], [%1], 16;" :: "r"(dst), "l"(src));
}
__device__ __forceinline__ void cp_commit() { asm volatile("cp.async.commit_group;"); }
__device__ __forceinline__ void cp_wait1()  { asm volatile("cp.async.wait_group 1;" ::: "memory"); }

__device__ __forceinline__ void ldsm4(uint32_t* r, uint32_t addr) {
    asm volatile("ldmatrix.sync.aligned.m8n8.x4.shared.b16 {%0,%1,%2,%3}, [%4];"
                 : "=r"(r[0]), "=r"(r[1]), "=r"(r[2]), "=r"(r[3]) : "r"(addr));
}
__device__ __forceinline__ void ldsm4t(uint32_t* r, uint32_t addr) {
    asm volatile("ldmatrix.sync.aligned.m8n8.x4.trans.shared.b16 {%0,%1,%2,%3}, [%4];"
                 : "=r"(r[0]), "=r"(r[1]), "=r"(r[2]), "=r"(r[3]) : "r"(addr));
}
__device__ __forceinline__ void mma_f16(float* c, const uint32_t* a, uint32_t b0, uint32_t b1) {
    asm volatile("mma.sync.aligned.m16n8k16.row.col.f32.f16.f16.f32 "
                 "{%0,%1,%2,%3}, {%4,%5,%6,%7}, {%8,%9}, {%0,%1,%2,%3};"
                 : "+f"(c[0]), "+f"(c[1]), "+f"(c[2]), "+f"(c[3])
                 : "r"(a[0]), "r"(a[1]), "r"(a[2]), "r"(a[3]), "r"(b0), "r"(b1));
}

// ---------------------------------------------------------------------------
// fp32 -> fp16 hi/lo split
// ---------------------------------------------------------------------------
__global__ __launch_bounds__(256)
void split_kernel(const float* __restrict__ src, __half* __restrict__ oh,
                  __half* __restrict__ ol)
{
    long long i = ((long long)blockIdx.x * 256 + threadIdx.x) * 4;
    float4 v = *(const float4*)(src + i);
    __half h0 = __float2half_rn(v.x), h1 = __float2half_rn(v.y);
    __half h2 = __float2half_rn(v.z), h3 = __float2half_rn(v.w);
    __half l0 = __float2half_rn(v.x - __half2float(h0));
    __half l1 = __float2half_rn(v.y - __half2float(h1));
    __half l2 = __float2half_rn(v.z - __half2float(h2));
    __half l3 = __float2half_rn(v.w - __half2float(h3));
    __half2 ha = __halves2half2(h0, h1), hb = __halves2half2(h2, h3);
    __half2 la = __halves2half2(l0, l1), lb = __halves2half2(l2, l3);
    *(uint2*)(oh + i) = make_uint2(*(uint32_t*)&ha, *(uint32_t*)&hb);
    *(uint2*)(ol + i) = make_uint2(*(uint32_t*)&la, *(uint32_t*)&lb);
}

// ---------------------------------------------------------------------------
// tile loaders, BK=32. K-major [128][32] 64B pitch swzK; MN-major [32][128]
// 256B pitch swzMN. 8 KB each.
// ---------------------------------------------------------------------------
__device__ __forceinline__ void load_opK(const __half* __restrict__ src, int ld,
                                         int x0, int k0, uint32_t dstb, int tid) {
#pragma unroll
    for (int it = 0; it < 2; it++) {
        int u = it * 256 + tid;
        int x = u >> 2, c = u & 3;
        cp16(dstb + swzK((uint32_t)(x * 64 + c * 16)),
             src + (long long)(x0 + x) * ld + k0 + c * 8);
    }
}
__device__ __forceinline__ void load_opMN(const __half* __restrict__ src, int ld,
                                          int x0, int k0, uint32_t dstb, int tid) {
#pragma unroll
    for (int it = 0; it < 2; it++) {
        int u = it * 256 + tid;
        int k = u >> 4, c = u & 15;
        cp16(dstb + swzMN((uint32_t)(k * 256 + c * 16)),
             src + (long long)(k0 + k) * ld + x0 + c * 8);
    }
}

#define OPQ 8192

// ---------------------------------------------------------------------------
// GEMM body. CHAINS=3: A,B fp16 hi/lo split (3 mma chains). CHAINS=1: plain
// fp16 (1 chain). CTA tile 128x128, BK=32, 8 warps 32x64, 3-stage cp.async.
// ---------------------------------------------------------------------------
template <int CHAINS>
__device__ __forceinline__ void gemm_body(
    const __half* pAH, const __half* pAL,
    const __half* pBH, const __half* pBL,
    float* C, int K, int lda, int ldb, int ldc,
    int m0, int n0, int amode, int bmode,
    uint32_t sb, int tid, int wid, int lane)
{
    constexpr uint32_t STAGEB = (CHAINS == 3) ? 4 * OPQ : 2 * OPQ;
    constexpr uint32_t BOFF   = (CHAINS == 3) ? 2 * OPQ : OPQ;
    const int wm = wid >> 1, wn = wid & 1;
    const int NKT = K >> 5;

    float acc[2][8][4];
#pragma unroll
    for (int t = 0; t < 2; t++)
#pragma unroll
        for (int q = 0; q < 8; q++)
#pragma unroll
            for (int e = 0; e < 4; e++) acc[t][q][e] = 0.f;

    auto load_stage = [&](int kt, int st) {
        uint32_t nb = sb + (uint32_t)st * STAGEB;
        int k0 = kt * 32;
        if (amode == 0) {
            load_opK(pAH, lda, m0, k0, nb, tid);
            if (CHAINS == 3) load_opK(pAL, lda, m0, k0, nb + OPQ, tid);
        } else {
            load_opMN(pAH, lda, m0, k0, nb, tid);
            if (CHAINS == 3) load_opMN(pAL, lda, m0, k0, nb + OPQ, tid);
        }
        if (bmode == 0) {
            load_opK(pBH, ldb, n0, k0, nb + BOFF, tid);
            if (CHAINS == 3) load_opK(pBL, ldb, n0, k0, nb + BOFF + OPQ, tid);
        } else {
            load_opMN(pBH, ldb, n0, k0, nb + BOFF, tid);
            if (CHAINS == 3) load_opMN(pBL, ldb, n0, k0, nb + BOFF + OPQ, tid);
        }
        cp_commit();
    };

    load_stage(0, 0);
    load_stage(1, 1);

    int st = 0;
    for (int kt = 0; kt < NKT; kt++) {
        cp_wait1();
        __syncthreads();
        if (kt + 2 < NKT) load_stage(kt + 2, (st + 2) % 3);

        const uint32_t tb = sb + (uint32_t)st * STAGEB;
        const uint32_t sAh = tb, sAl = tb + OPQ;
        const uint32_t sBh = tb + BOFF, sBl = tb + BOFF + OPQ;
#pragma unroll
        for (int ks = 0; ks < 2; ks++) {
            uint32_t a_hi[2][4], a_lo[2][4];
#pragma unroll
            for (int t = 0; t < 2; t++) {
                if (amode == 0) {
                    uint32_t off = (uint32_t)((wm * 32 + t * 16 + (lane & 15)) * 64
                                              + ks * 32 + (lane >> 4) * 16);
                    uint32_t sw = swzK(off);
                    ldsm4(a_hi[t], sAh + sw);
                    if (CHAINS == 3) ldsm4(a_lo[t], sAl + sw);
                } else {
                    uint32_t off = (uint32_t)((ks * 16 + (lane & 7) + ((lane >> 4) & 1) * 8) * 256
                                              + (wm * 32 + t * 16 + ((lane >> 3) & 1) * 8) * 2);
                    uint32_t sw = swzMN(off);
                    ldsm4t(a_hi[t], sAh + sw);
                    if (CHAINS == 3) ldsm4t(a_lo[t], sAl + sw);
                }
            }
#pragma unroll
            for (int p = 0; p < 4; p++) {
                uint32_t b_hi[4], b_lo[4];
                if (bmode == 0) {
                    uint32_t off = (uint32_t)((wn * 64 + p * 16 + (lane & 7) + ((lane >> 4) << 3)) * 64
                                              + ks * 32 + ((lane >> 3) & 1) * 16);
                    uint32_t sw = swzK(off);
                    ldsm4(b_hi, sBh + sw);
                    if (CHAINS == 3) ldsm4(b_lo, sBl + sw);
                } else {
                    uint32_t off = (uint32_t)((ks * 16 + (lane & 15)) * 256
                                              + (wn * 64 + p * 16 + (lane >> 4) * 8) * 2);
                    uint32_t sw = swzMN(off);
                    ldsm4t(b_hi, sBh + sw);
                    if (CHAINS == 3) ldsm4t(b_lo, sBl + sw);
                }
#pragma unroll
                for (int t = 0; t < 2; t++)
#pragma unroll
                    for (int qq = 0; qq < 2; qq++) {
                        const int q = p * 2 + qq, h = qq * 2;
                        mma_f16(acc[t][q], a_hi[t], b_hi[h], b_hi[h + 1]);
                        if (CHAINS == 3) {
                            mma_f16(acc[t][q], a_hi[t], b_lo[h], b_lo[h + 1]);
                            mma_f16(acc[t][q], a_lo[t], b_hi[h], b_hi[h + 1]);
                        }
                    }
            }
        }
        st = (st + 1) % 3;
    }

    const int row0 = lane >> 2, col0 = (lane & 3) * 2;
#pragma unroll
    for (int t = 0; t < 2; t++) {
        const int r = m0 + wm * 32 + t * 16 + row0;
#pragma unroll
        for (int q = 0; q < 8; q++) {
            const int c = n0 + wn * 64 + q * 8 + col0;
            *(float2*)&C[(long long)r * ldc + c] = make_float2(acc[t][q][0], acc[t][q][1]);
            *(float2*)&C[(long long)(r + 8) * ldc + c] = make_float2(acc[t][q][2], acc[t][q][3]);
        }
    }
}

#define SMEM_G1  (3 * 4 * OPQ)    // 96 KB (3-chain stages)
#define SMEM_G23 (3 * 4 * OPQ)    // 96 KB (max of 1-chain/3-chain branches)

// ---------------------------------------------------------------------------
// GEMM1: S = prem @ hyp^T (both K-major, fp16 hi/lo 3-chain), K=512
// ---------------------------------------------------------------------------
__global__ void __launch_bounds__(256, 2)
gemm1_kernel(const __half* __restrict__ AHp, const __half* __restrict__ ALp,
             const __half* __restrict__ BHp, const __half* __restrict__ BLp,
             float* __restrict__ Sp)
{
    extern __shared__ char smem[];
    const uint32_t sb = smem_u32(smem);
    const int tid = threadIdx.x, wid = tid >> 5, lane = tid & 31;
    const long long b = blockIdx.z;
    gemm_body<3>(AHp + b * (LA * HD), ALp + b * (LA * HD),
                 BHp + b * (LB * HD), BLp + b * (LB * HD),
                 Sp + b * (LA * LB),
                 HD, HD, HD, LB,
                 blockIdx.y * 128, blockIdx.x * 128, 0, 0, sb, tid, wid, lane);
}

// ---------------------------------------------------------------------------
// Fused GEMM2+GEMM3.
// z < NB : AP = P @ hyp        (1 chain:  P fp16, hyp hi)      -- proven 2.5e-4
// z >= NB: AH = Q^T @ prem     (3 chains: Q hi/lo, prem hi/lo) -- proven 2.3e-5
// ---------------------------------------------------------------------------
__global__ void __launch_bounds__(256, 2)
gemm23_kernel(const __half* __restrict__ Pp,
              const __half* __restrict__ QHp, const __half* __restrict__ QLp,
              const __half* __restrict__ hyHp,
              const __half* __restrict__ pmHp, const __half* __restrict__ pmLp,
              float* __restrict__ APp, float* __restrict__ AHp)
{
    extern __shared__ char smem[];
    const uint32_t sb = smem_u32(smem);
    const int tid = threadIdx.x, wid = tid >> 5, lane = tid & 31;
    const int z = blockIdx.z;
    if (z < NB) {
        const long long b = z;
        gemm_body<1>(Pp + b * (LA * LB), nullptr,
                     hyHp + b * (LB * HD), nullptr,
                     APp + b * (LA * HD),
                     LB, LB, HD, HD,
                     blockIdx.y * 128, blockIdx.x * 128, 0, 1, sb, tid, wid, lane);
    } else {
        const long long b = z - NB;
        gemm_body<3>(QHp + b * (LA * LB), QLp + b * (LA * LB),
                     pmHp + b * (LA * HD), pmLp + b * (LA * HD),
                     AHp + b * (LB * HD),
                     LA, LB, HD, HD,
                     blockIdx.y * 128, blockIdx.x * 128, 1, 1, sb, tid, wid, lane);
    }
}

// ---------------------------------------------------------------------------
// Fused softmax: blockIdx.x < LA -> row block (P fp16 single);
//                else            -> col block (Q fp16 hi/lo).
// ---------------------------------------------------------------------------
__global__ __launch_bounds__(256)
void softmax_kernel(const float* __restrict__ S,
                    __half* __restrict__ P,
                    __half* __restrict__ QH, __half* __restrict__ QL,
                    const float* __restrict__ pmask, const float* __restrict__ hmask)
{
    const int b = blockIdx.y;
    const int tid = threadIdx.x;
    __shared__ float shm[3][8][32];

    if (blockIdx.x < LA) {
        const int i = blockIdx.x;
        const long long rowoff = ((long long)b * LA + i) * LB;

        float4 s = *(const float4*)&S[rowoff + tid * 4];
        float4 h = *(const float4*)&hmask[(long long)b * LB + tid * 4];
        float l0 = s.x * h.x, l1 = s.y * h.y, l2 = s.z * h.z, l3 = s.w * h.w;

        float v = fmaxf(fmaxf(l0, l1), fmaxf(l2, l3));
#pragma unroll
        for (int o = 16; o; o >>= 1) v = fmaxf(v, __shfl_xor_sync(0xffffffffu, v, o));
        if ((tid & 31) == 0) shm[0][0][tid >> 5] = v;
        __syncthreads();
        float m = shm[0][0][0];
#pragma unroll
        for (int w = 1; w < 8; w++) m = fmaxf(m, shm[0][0][w]);
        __syncthreads();

        float e0 = __expf(l0 - m), e1 = __expf(l1 - m), e2 = __expf(l2 - m), e3 = __expf(l3 - m);
        float d = e0 + e1 + e2 + e3;
        float e = h.x * e0 + h.y * e1 + h.z * e2 + h.w * e3;
#pragma unroll
        for (int o = 16; o; o >>= 1) {
            d += __shfl_xor_sync(0xffffffffu, d, o);
            e += __shfl_xor_sync(0xffffffffu, e, o);
        }
        if ((tid & 31) == 0) { shm[0][0][tid >> 5] = d; shm[0][1][tid >> 5] = e; }
        __syncthreads();
        float D = 0.f, E = 0.f;
#pragma unroll
        for (int w = 0; w < 8; w++) { D += shm[0][0][w]; E += shm[0][1][w]; }

        const float pm = pmask[(long long)b * LA + i];
        const float scale = pm / (E + EPSV * D);

        __half2 o01 = __floats2half2_rn(h.x * e0 * scale, h.y * e1 * scale);
        __half2 o23 = __floats2half2_rn(h.z * e2 * scale, h.w * e3 * scale);
        *(uint2*)&P[rowoff + tid * 4] = make_uint2(*(uint32_t*)&o01, *(uint32_t*)&o23);
    } else {
        const int tx = tid & 31, ty = tid >> 5;
        const int j = (blockIdx.x - LA) * 32 + tx;
        const float* Sb = S + (long long)b * LA * LB;
        __half* Qh = QH + (long long)b * LA * LB;
        __half* Ql = QL + (long long)b * LA * LB;
        const float* pm = pmask + (long long)b * LA;

        float m = -1e30f, D = 0.f, E = 0.f;
        for (int r = ty; r < LA; r += 8) {
            float pmr = pm[r];
            float l = Sb[(long long)r * LB + j] * pmr;
            if (l <= m) {
                float ev = __expf(l - m);
                D += ev; E += pmr * ev;
            } else {
                float f = __expf(m - l);
                D = D * f + 1.f;
                E = E * f + pmr;
                m = l;
            }
        }
        shm[0][ty][tx] = m; shm[1][ty][tx] = D; shm[2][ty][tx] = E;
        __syncthreads();
        float M = shm[0][0][tx];
#pragma unroll
        for (int t = 1; t < 8; t++) M = fmaxf(M, shm[0][t][tx]);
        float Dt = 0.f, Et = 0.f;
#pragma unroll
        for (int t = 0; t < 8; t++) {
            float f = __expf(shm[0][t][tx] - M);
            Dt += shm[1][t][tx] * f;
            Et += shm[2][t][tx] * f;
        }

        const float scale = hmask[(long long)b * LB + j] / (Et + EPSV * Dt);

        for (int r = ty; r < LA; r += 8) {
            float pmr = pm[r];
            float ev = __expf(Sb[(long long)r * LB + j] * pmr - M);
            float val = pmr * ev * scale;
            __half hh = __float2half_rn(val);
            __half ll = __float2half_rn(val - __half2float(hh));
            Qh[(long long)r * LB + j] = hh;
            Ql[(long long)r * LB + j] = ll;
        }
    }
}

// ---------------------------------------------------------------------------
extern "C" void kernel_launch(void* const* d_in, const int* in_sizes, int n_in,
                              void* d_out, int out_size)
{
    const float* prem  = (const float*)d_in[0];
    const float* pmask = (const float*)d_in[1];
    const float* hyp   = (const float*)d_in[2];
    const float* hmask = (const float*)d_in[3];

    float* AP  = (float*)d_out;
    float* AHo = AP + (long long)NB * LA * HD;

    void *pS, *pP, *pQH, *pQL, *ppmH, *ppmL, *phyH, *phyL;
    cudaGetSymbolAddress(&pS, g_S);
    cudaGetSymbolAddress(&pP, g_P);
    cudaGetSymbolAddress(&pQH, g_QH); cudaGetSymbolAddress(&pQL, g_QL);
    cudaGetSymbolAddress(&ppmH, g_pmH); cudaGetSymbolAddress(&ppmL, g_pmL);
    cudaGetSymbolAddress(&phyH, g_hyH); cudaGetSymbolAddress(&phyL, g_hyL);
    float* S = (float*)pS;
    __half *P = (__half*)pP;
    __half *QH = (__half*)pQH, *QL = (__half*)pQL;
    __half *pmH = (__half*)ppmH, *pmL = (__half*)ppmL;
    __half *hyH = (__half*)phyH, *hyL = (__half*)phyL;

    cudaFuncSetAttribute(gemm1_kernel,  cudaFuncAttributeMaxDynamicSharedMemorySize, SMEM_G1);
    cudaFuncSetAttribute(gemm23_kernel, cudaFuncAttributeMaxDynamicSharedMemorySize, SMEM_G23);

    // 0) split inputs into fp16 hi/lo
    {
        int nblk = (int)((long long)NB * LA * HD / 1024);
        split_kernel<<<nblk, 256>>>(prem, pmH, pmL);
        split_kernel<<<nblk, 256>>>(hyp, hyH, hyL);
    }
    // 1) S = prem @ hyp^T  (K=512, 3-chain fp16)
    {
        dim3 grid(LB / 128, LA / 128, NB);
        gemm1_kernel<<<grid, 256, SMEM_G1>>>(pmH, pmL, hyH, hyL, S);
    }
    // 2) fused row+col masked softmax -> P (fp16), Q (fp16 hi/lo)
    {
        dim3 grid(LA + LB / 32, NB);
        softmax_kernel<<<grid, 256>>>(S, P, QH, QL, pmask, hmask);
    }
    // 3) fused GEMM2+GEMM3 -> AP (1-chain), AH (3-chain)
    {
        dim3 grid(HD / 128, LA / 128, 2 * NB);
        gemm23_kernel<<<grid, 256, SMEM_G23>>>(P, QH, QL, hyH, pmH, pmL, AP, AHo);
    }
}

// round 15
// speedup vs baseline: 3.4779x; 1.0253x over previous
#include <cuda_runtime.h>
#include <cuda_fp16.h>
#include <cstdint>

#define NB 16
#define LA 1024
#define LB 1024
#define HD 512
#define EPSV 1e-13f

__device__ float  g_S [(long long)NB * LA * LB];
__device__ __half g_P [(long long)NB * LA * LB];    // row-softmax out (fp16, normalized)
__device__ __half g_QH[(long long)NB * LA * LB];    // col-softmax out hi (UNNORMALIZED)
__device__ __half g_QL[(long long)NB * LA * LB];    // col-softmax out lo (UNNORMALIZED)
__device__ float  g_scQ[(long long)NB * LB];        // per-column scale for Q
__device__ __half g_pmH[(long long)NB * LA * HD];
__device__ __half g_pmL[(long long)NB * LA * HD];
__device__ __half g_hyH[(long long)NB * LB * HD];
__device__ __half g_hyL[(long long)NB * LB * HD];

// ---------------------------------------------------------------------------
__device__ __forceinline__ uint32_t smem_u32(const void* p) {
    uint32_t a;
    asm("{ .reg .u64 t; cvta.to.shared.u64 t, %1; cvt.u32.u64 %0, t; }" : "=r"(a) : "l"(p));
    return a;
}
__device__ __forceinline__ uint32_t swzMN(uint32_t off) { return off ^ ((off >> 4) & 0x70); }
__device__ __forceinline__ uint32_t swzK(uint32_t off)  { return off ^ (((off >> 7) & 0x3) << 4); }

__device__ __forceinline__ void cp16(uint32_t dst, const void* src) {
    asm volatile("cp.async.cg.shared.global [%0], [%1], 16;" :: "r"(dst), "l"(src));
}
__device__ __forceinline__ void cp_commit() { asm volatile("cp.async.commit_group;"); }
__device__ __forceinline__ void cp_wait1()  { asm volatile("cp.async.wait_group 1;" ::: "memory"); }

__device__ __forceinline__ void ldsm4(uint32_t* r, uint32_t addr) {
    asm volatile("ldmatrix.sync.aligned.m8n8.x4.shared.b16 {%0,%1,%2,%3}, [%4];"
                 : "=r"(r[0]), "=r"(r[1]), "=r"(r[2]), "=r"(r[3]) : "r"(addr));
}
__device__ __forceinline__ void ldsm4t(uint32_t* r, uint32_t addr) {
    asm volatile("ldmatrix.sync.aligned.m8n8.x4.trans.shared.b16 {%0,%1,%2,%3}, [%4];"
                 : "=r"(r[0]), "=r"(r[1]), "=r"(r[2]), "=r"(r[3]) : "r"(addr));
}
__device__ __forceinline__ void mma_f16(float* c, const uint32_t* a, uint32_t b0, uint32_t b1) {
    asm volatile("mma.sync.aligned.m16n8k16.row.col.f32.f16.f16.f32 "
                 "{%0,%1,%2,%3}, {%4,%5,%6,%7}, {%8,%9}, {%0,%1,%2,%3};"
                 : "+f"(c[0]), "+f"(c[1]), "+f"(c[2]), "+f"(c[3])
                 : "r"(a[0]), "r"(a[1]), "r"(a[2]), "r"(a[3]), "r"(b0), "r"(b1));
}
// fp16 accumulator variant (d/c packed half2 x2)
__device__ __forceinline__ void mma_f16h(uint32_t* c, const uint32_t* a, uint32_t b0, uint32_t b1) {
    asm volatile("mma.sync.aligned.m16n8k16.row.col.f16.f16.f16.f16 "
                 "{%0,%1}, {%2,%3,%4,%5}, {%6,%7}, {%0,%1};"
                 : "+r"(c[0]), "+r"(c[1])
                 : "r"(a[0]), "r"(a[1]), "r"(a[2]), "r"(a[3]), "r"(b0), "r"(b1));
}

// ---------------------------------------------------------------------------
__global__ __launch_bounds__(256)
void split_kernel(const float* __restrict__ src, __half* __restrict__ oh,
                  __half* __restrict__ ol)
{
    long long i = ((long long)blockIdx.x * 256 + threadIdx.x) * 4;
    float4 v = *(const float4*)(src + i);
    __half h0 = __float2half_rn(v.x), h1 = __float2half_rn(v.y);
    __half h2 = __float2half_rn(v.z), h3 = __float2half_rn(v.w);
    __half l0 = __float2half_rn(v.x - __half2float(h0));
    __half l1 = __float2half_rn(v.y - __half2float(h1));
    __half l2 = __float2half_rn(v.z - __half2float(h2));
    __half l3 = __float2half_rn(v.w - __half2float(h3));
    __half2 ha = __halves2half2(h0, h1), hb = __halves2half2(h2, h3);
    __half2 la = __halves2half2(l0, l1), lb = __halves2half2(l2, l3);
    *(uint2*)(oh + i) = make_uint2(*(uint32_t*)&ha, *(uint32_t*)&hb);
    *(uint2*)(ol + i) = make_uint2(*(uint32_t*)&la, *(uint32_t*)&lb);
}

// ---------------------------------------------------------------------------
__device__ __forceinline__ void load_opK(const __half* __restrict__ src, int ld,
                                         int x0, int k0, uint32_t dstb, int tid) {
#pragma unroll
    for (int it = 0; it < 2; it++) {
        int u = it * 256 + tid;
        int x = u >> 2, c = u & 3;
        cp16(dstb + swzK((uint32_t)(x * 64 + c * 16)),
             src + (long long)(x0 + x) * ld + k0 + c * 8);
    }
}
__device__ __forceinline__ void load_opMN(const __half* __restrict__ src, int ld,
                                          int x0, int k0, uint32_t dstb, int tid) {
#pragma unroll
    for (int it = 0; it < 2; it++) {
        int u = it * 256 + tid;
        int k = u >> 4, c = u & 15;
        cp16(dstb + swzMN((uint32_t)(k * 256 + c * 16)),
             src + (long long)(k0 + k) * ld + x0 + c * 8);
    }
}

#define OPQ 8192

// ---------------------------------------------------------------------------
// fp32-acc GEMM body (CHAINS = 1 or 3), optional per-output-row scale.
// ---------------------------------------------------------------------------
template <int CHAINS>
__device__ __forceinline__ void gemm_body(
    const __half* pAH, const __half* pAL,
    const __half* pBH, const __half* pBL,
    float* C, int K, int lda, int ldb, int ldc,
    int m0, int n0, int amode, int bmode,
    const float* rowscale,
    uint32_t sb, int tid, int wid, int lane)
{
    constexpr uint32_t STAGEB = (CHAINS == 3) ? 4 * OPQ : 2 * OPQ;
    constexpr uint32_t BOFF   = (CHAINS == 3) ? 2 * OPQ : OPQ;
    const int wm = wid >> 1, wn = wid & 1;
    const int NKT = K >> 5;

    float acc[2][8][4];
#pragma unroll
    for (int t = 0; t < 2; t++)
#pragma unroll
        for (int q = 0; q < 8; q++)
#pragma unroll
            for (int e = 0; e < 4; e++) acc[t][q][e] = 0.f;

    auto load_stage = [&](int kt, int st) {
        uint32_t nb = sb + (uint32_t)st * STAGEB;
        int k0 = kt * 32;
        if (amode == 0) {
            load_opK(pAH, lda, m0, k0, nb, tid);
            if (CHAINS == 3) load_opK(pAL, lda, m0, k0, nb + OPQ, tid);
        } else {
            load_opMN(pAH, lda, m0, k0, nb, tid);
            if (CHAINS == 3) load_opMN(pAL, lda, m0, k0, nb + OPQ, tid);
        }
        if (bmode == 0) {
            load_opK(pBH, ldb, n0, k0, nb + BOFF, tid);
            if (CHAINS == 3) load_opK(pBL, ldb, n0, k0, nb + BOFF + OPQ, tid);
        } else {
            load_opMN(pBH, ldb, n0, k0, nb + BOFF, tid);
            if (CHAINS == 3) load_opMN(pBL, ldb, n0, k0, nb + BOFF + OPQ, tid);
        }
        cp_commit();
    };

    load_stage(0, 0);
    load_stage(1, 1);

    int st = 0;
    for (int kt = 0; kt < NKT; kt++) {
        cp_wait1();
        __syncthreads();
        if (kt + 2 < NKT) load_stage(kt + 2, (st + 2) % 3);

        const uint32_t tb = sb + (uint32_t)st * STAGEB;
        const uint32_t sAh = tb, sAl = tb + OPQ;
        const uint32_t sBh = tb + BOFF, sBl = tb + BOFF + OPQ;
#pragma unroll
        for (int ks = 0; ks < 2; ks++) {
            uint32_t a_hi[2][4], a_lo[2][4];
#pragma unroll
            for (int t = 0; t < 2; t++) {
                if (amode == 0) {
                    uint32_t off = (uint32_t)((wm * 32 + t * 16 + (lane & 15)) * 64
                                              + ks * 32 + (lane >> 4) * 16);
                    uint32_t sw = swzK(off);
                    ldsm4(a_hi[t], sAh + sw);
                    if (CHAINS == 3) ldsm4(a_lo[t], sAl + sw);
                } else {
                    uint32_t off = (uint32_t)((ks * 16 + (lane & 7) + ((lane >> 4) & 1) * 8) * 256
                                              + (wm * 32 + t * 16 + ((lane >> 3) & 1) * 8) * 2);
                    uint32_t sw = swzMN(off);
                    ldsm4t(a_hi[t], sAh + sw);
                    if (CHAINS == 3) ldsm4t(a_lo[t], sAl + sw);
                }
            }
#pragma unroll
            for (int p = 0; p < 4; p++) {
                uint32_t b_hi[4], b_lo[4];
                if (bmode == 0) {
                    uint32_t off = (uint32_t)((wn * 64 + p * 16 + (lane & 7) + ((lane >> 4) << 3)) * 64
                                              + ks * 32 + ((lane >> 3) & 1) * 16);
                    uint32_t sw = swzK(off);
                    ldsm4(b_hi, sBh + sw);
                    if (CHAINS == 3) ldsm4(b_lo, sBl + sw);
                } else {
                    uint32_t off = (uint32_t)((ks * 16 + (lane & 15)) * 256
                                              + (wn * 64 + p * 16 + (lane >> 4) * 8) * 2);
                    uint32_t sw = swzMN(off);
                    ldsm4t(b_hi, sBh + sw);
                    if (CHAINS == 3) ldsm4t(b_lo, sBl + sw);
                }
#pragma unroll
                for (int t = 0; t < 2; t++)
#pragma unroll
                    for (int qq = 0; qq < 2; qq++) {
                        const int q = p * 2 + qq, h = qq * 2;
                        mma_f16(acc[t][q], a_hi[t], b_hi[h], b_hi[h + 1]);
                        if (CHAINS == 3) {
                            mma_f16(acc[t][q], a_hi[t], b_lo[h], b_lo[h + 1]);
                            mma_f16(acc[t][q], a_lo[t], b_hi[h], b_hi[h + 1]);
                        }
                    }
            }
        }
        st = (st + 1) % 3;
    }

    const int row0 = lane >> 2, col0 = (lane & 3) * 2;
#pragma unroll
    for (int t = 0; t < 2; t++) {
        const int r = m0 + wm * 32 + t * 16 + row0;
        float s0 = 1.f, s1 = 1.f;
        if (rowscale) { s0 = rowscale[r]; s1 = rowscale[r + 8]; }
#pragma unroll
        for (int q = 0; q < 8; q++) {
            const int c = n0 + wn * 64 + q * 8 + col0;
            *(float2*)&C[(long long)r * ldc + c] =
                make_float2(acc[t][q][0] * s0, acc[t][q][1] * s0);
            *(float2*)&C[(long long)(r + 8) * ldc + c] =
                make_float2(acc[t][q][2] * s1, acc[t][q][3] * s1);
        }
    }
}

// ---------------------------------------------------------------------------
// fp16-acc GEMM body: 1 chain, A K-major, B MN-major (G2 specialization).
// ---------------------------------------------------------------------------
__device__ __forceinline__ void gemm_body_h(
    const __half* pA, const __half* pB,
    float* C, int K, int lda, int ldb, int ldc,
    int m0, int n0,
    uint32_t sb, int tid, int wid, int lane)
{
    constexpr uint32_t STAGEB = 2 * OPQ;
    const int wm = wid >> 1, wn = wid & 1;
    const int NKT = K >> 5;

    uint32_t acc[2][8][2];
#pragma unroll
    for (int t = 0; t < 2; t++)
#pragma unroll
        for (int q = 0; q < 8; q++) { acc[t][q][0] = 0u; acc[t][q][1] = 0u; }

    auto load_stage = [&](int kt, int st) {
        uint32_t nb = sb + (uint32_t)st * STAGEB;
        int k0 = kt * 32;
        load_opK(pA, lda, m0, k0, nb, tid);
        load_opMN(pB, ldb, n0, k0, nb + OPQ, tid);
        cp_commit();
    };

    load_stage(0, 0);
    load_stage(1, 1);

    int st = 0;
    for (int kt = 0; kt < NKT; kt++) {
        cp_wait1();
        __syncthreads();
        if (kt + 2 < NKT) load_stage(kt + 2, (st + 2) % 3);

        const uint32_t tb = sb + (uint32_t)st * STAGEB;
        const uint32_t sA = tb, sB = tb + OPQ;
#pragma unroll
        for (int ks = 0; ks < 2; ks++) {
            uint32_t a[2][4];
#pragma unroll
            for (int t = 0; t < 2; t++) {
                uint32_t off = (uint32_t)((wm * 32 + t * 16 + (lane & 15)) * 64
                                          + ks * 32 + (lane >> 4) * 16);
                ldsm4(a[t], sA + swzK(off));
            }
#pragma unroll
            for (int p = 0; p < 4; p++) {
                uint32_t bfr[4];
                uint32_t off = (uint32_t)((ks * 16 + (lane & 15)) * 256
                                          + (wn * 64 + p * 16 + (lane >> 4) * 8) * 2);
                ldsm4t(bfr, sB + swzMN(off));
#pragma unroll
                for (int t = 0; t < 2; t++)
#pragma unroll
                    for (int qq = 0; qq < 2; qq++) {
                        const int q = p * 2 + qq, h = qq * 2;
                        mma_f16h(acc[t][q], a[t], bfr[h], bfr[h + 1]);
                    }
            }
        }
        st = (st + 1) % 3;
    }

    const int row0 = lane >> 2, col0 = (lane & 3) * 2;
#pragma unroll
    for (int t = 0; t < 2; t++) {
        const int r = m0 + wm * 32 + t * 16 + row0;
#pragma unroll
        for (int q = 0; q < 8; q++) {
            const int c = n0 + wn * 64 + q * 8 + col0;
            float2 f0 = __half22float2(*(__half2*)&acc[t][q][0]);
            float2 f1 = __half22float2(*(__half2*)&acc[t][q][1]);
            *(float2*)&C[(long long)r * ldc + c] = f0;
            *(float2*)&C[(long long)(r + 8) * ldc + c] = f1;
        }
    }
}

#define SMEM_G1  (3 * 4 * OPQ)    // 96 KB
#define SMEM_G23 (3 * 4 * OPQ)    // 96 KB

// ---------------------------------------------------------------------------
__global__ void __launch_bounds__(256, 2)
gemm1_kernel(const __half* __restrict__ AHp, const __half* __restrict__ ALp,
             const __half* __restrict__ BHp, const __half* __restrict__ BLp,
             float* __restrict__ Sp)
{
    extern __shared__ char smem[];
    const uint32_t sb = smem_u32(smem);
    const int tid = threadIdx.x, wid = tid >> 5, lane = tid & 31;
    const long long b = blockIdx.z;
    gemm_body<3>(AHp + b * (LA * HD), ALp + b * (LA * HD),
                 BHp + b * (LB * HD), BLp + b * (LB * HD),
                 Sp + b * (LA * LB),
                 HD, HD, HD, LB,
                 blockIdx.y * 128, blockIdx.x * 128, 0, 0, nullptr, sb, tid, wid, lane);
}

// ---------------------------------------------------------------------------
// z < NB : AP = P @ hyp         (1 chain, f16 acc)
// z >= NB: AH = scQ * (U^T @ prem)  (3 chains, f32 acc, col-scale in epilogue)
// ---------------------------------------------------------------------------
__global__ void __launch_bounds__(256, 2)
gemm23_kernel(const __half* __restrict__ Pp,
              const __half* __restrict__ QHp, const __half* __restrict__ QLp,
              const __half* __restrict__ hyHp,
              const __half* __restrict__ pmHp, const __half* __restrict__ pmLp,
              const float* __restrict__ scQp,
              float* __restrict__ APp, float* __restrict__ AHp)
{
    extern __shared__ char smem[];
    const uint32_t sb = smem_u32(smem);
    const int tid = threadIdx.x, wid = tid >> 5, lane = tid & 31;
    const int z = blockIdx.z;
    if (z < NB) {
        const long long b = z;
        gemm_body_h(Pp + b * (LA * LB),
                    hyHp + b * (LB * HD),
                    APp + b * (LA * HD),
                    LB, LB, HD, HD,
                    blockIdx.y * 128, blockIdx.x * 128, sb, tid, wid, lane);
    } else {
        const long long b = z - NB;
        gemm_body<3>(QHp + b * (LA * LB), QLp + b * (LA * LB),
                     pmHp + b * (LA * HD), pmLp + b * (LA * HD),
                     AHp + b * (LB * HD),
                     LA, LB, HD, HD,
                     blockIdx.y * 128, blockIdx.x * 128, 1, 1,
                     scQp + b * LB, sb, tid, wid, lane);
    }
}

// ---------------------------------------------------------------------------
// Fused softmax. Row blocks: normalized P (fp16). Col blocks: max pass (no
// exp) + single exp pass writing UNNORMALIZED U hi/lo + per-column scale.
// ---------------------------------------------------------------------------
__global__ __launch_bounds__(256)
void softmax_kernel(const float* __restrict__ S,
                    __half* __restrict__ P,
                    __half* __restrict__ QH, __half* __restrict__ QL,
                    float* __restrict__ scQ,
                    const float* __restrict__ pmask, const float* __restrict__ hmask)
{
    const int b = blockIdx.y;
    const int tid = threadIdx.x;
    __shared__ float shm[3][8][32];

    if (blockIdx.x < LA) {
        const int i = blockIdx.x;
        const long long rowoff = ((long long)b * LA + i) * LB;

        float4 s = *(const float4*)&S[rowoff + tid * 4];
        float4 h = *(const float4*)&hmask[(long long)b * LB + tid * 4];
        float l0 = s.x * h.x, l1 = s.y * h.y, l2 = s.z * h.z, l3 = s.w * h.w;

        float v = fmaxf(fmaxf(l0, l1), fmaxf(l2, l3));
#pragma unroll
        for (int o = 16; o; o >>= 1) v = fmaxf(v, __shfl_xor_sync(0xffffffffu, v, o));
        if ((tid & 31) == 0) shm[0][0][tid >> 5] = v;
        __syncthreads();
        float m = shm[0][0][0];
#pragma unroll
        for (int w = 1; w < 8; w++) m = fmaxf(m, shm[0][0][w]);
        __syncthreads();

        float e0 = __expf(l0 - m), e1 = __expf(l1 - m), e2 = __expf(l2 - m), e3 = __expf(l3 - m);
        float d = e0 + e1 + e2 + e3;
        float e = h.x * e0 + h.y * e1 + h.z * e2 + h.w * e3;
#pragma unroll
        for (int o = 16; o; o >>= 1) {
            d += __shfl_xor_sync(0xffffffffu, d, o);
            e += __shfl_xor_sync(0xffffffffu, e, o);
        }
        if ((tid & 31) == 0) { shm[0][0][tid >> 5] = d; shm[0][1][tid >> 5] = e; }
        __syncthreads();
        float D = 0.f, E = 0.f;
#pragma unroll
        for (int w = 0; w < 8; w++) { D += shm[0][0][w]; E += shm[0][1][w]; }

        const float pm = pmask[(long long)b * LA + i];
        const float scale = pm / (E + EPSV * D);

        __half2 o01 = __floats2half2_rn(h.x * e0 * scale, h.y * e1 * scale);
        __half2 o23 = __floats2half2_rn(h.z * e2 * scale, h.w * e3 * scale);
        *(uint2*)&P[rowoff + tid * 4] = make_uint2(*(uint32_t*)&o01, *(uint32_t*)&o23);
    } else {
        const int tx = tid & 31, ty = tid >> 5;
        const int j = (blockIdx.x - LA) * 32 + tx;
        const float* Sb = S + (long long)b * LA * LB;
        __half* Qh = QH + (long long)b * LA * LB;
        __half* Ql = QL + (long long)b * LA * LB;
        const float* pm = pmask + (long long)b * LA;

        // pass 1: max only (no exp)
        float m = -1e30f;
        for (int r = ty; r < LA; r += 8)
            m = fmaxf(m, Sb[(long long)r * LB + j] * pm[r]);
        shm[0][ty][tx] = m;
        __syncthreads();
        float M = shm[0][0][tx];
#pragma unroll
        for (int t = 1; t < 8; t++) M = fmaxf(M, shm[0][t][tx]);

        // pass 2: exp + sums + write unnormalized U
        float D = 0.f, E = 0.f;
        for (int r = ty; r < LA; r += 8) {
            float pmr = pm[r];
            float ev = __expf(Sb[(long long)r * LB + j] * pmr - M);
            D += ev;
            float u = pmr * ev;
            E += u;
            __half hh = __float2half_rn(u);
            Qh[(long long)r * LB + j] = hh;
            Ql[(long long)r * LB + j] = __float2half_rn(u - __half2float(hh));
        }
        shm[1][ty][tx] = D; shm[2][ty][tx] = E;
        __syncthreads();
        float Dt = 0.f, Et = 0.f;
#pragma unroll
        for (int t = 0; t < 8; t++) { Dt += shm[1][t][tx]; Et += shm[2][t][tx]; }

        if (ty == 0)
            scQ[(long long)b * LB + j] = hmask[(long long)b * LB + j] / (Et + EPSV * Dt);
    }
}

// ---------------------------------------------------------------------------
extern "C" void kernel_launch(void* const* d_in, const int* in_sizes, int n_in,
                              void* d_out, int out_size)
{
    const float* prem  = (const float*)d_in[0];
    const float* pmask = (const float*)d_in[1];
    const float* hyp   = (const float*)d_in[2];
    const float* hmask = (const float*)d_in[3];

    float* AP  = (float*)d_out;
    float* AHo = AP + (long long)NB * LA * HD;

    void *pS, *pP, *pQH, *pQL, *pscQ, *ppmH, *ppmL, *phyH, *phyL;
    cudaGetSymbolAddress(&pS, g_S);
    cudaGetSymbolAddress(&pP, g_P);
    cudaGetSymbolAddress(&pQH, g_QH); cudaGetSymbolAddress(&pQL, g_QL);
    cudaGetSymbolAddress(&pscQ, g_scQ);
    cudaGetSymbolAddress(&ppmH, g_pmH); cudaGetSymbolAddress(&ppmL, g_pmL);
    cudaGetSymbolAddress(&phyH, g_hyH); cudaGetSymbolAddress(&phyL, g_hyL);
    float* S = (float*)pS;
    __half *P = (__half*)pP;
    __half *QH = (__half*)pQH, *QL = (__half*)pQL;
    float* scQ = (float*)pscQ;
    __half *pmH = (__half*)ppmH, *pmL = (__half*)ppmL;
    __half *hyH = (__half*)phyH, *hyL = (__half*)phyL;

    cudaFuncSetAttribute(gemm1_kernel,  cudaFuncAttributeMaxDynamicSharedMemorySize, SMEM_G1);
    cudaFuncSetAttribute(gemm23_kernel, cudaFuncAttributeMaxDynamicSharedMemorySize, SMEM_G23);

    // 0) split inputs into fp16 hi/lo
    {
        int nblk = (int)((long long)NB * LA * HD / 1024);
        split_kernel<<<nblk, 256>>>(prem, pmH, pmL);
        split_kernel<<<nblk, 256>>>(hyp, hyH, hyL);
    }
    // 1) S = prem @ hyp^T  (K=512, 3-chain fp16, fp32 acc)
    {
        dim3 grid(LB / 128, LA / 128, NB);
        gemm1_kernel<<<grid, 256, SMEM_G1>>>(pmH, pmL, hyH, hyL, S);
    }
    // 2) fused softmax -> P (normalized fp16), U hi/lo + scQ (col direction)
    {
        dim3 grid(LA + LB / 32, NB);
        softmax_kernel<<<grid, 256>>>(S, P, QH, QL, scQ, pmask, hmask);
    }
    // 3) fused GEMM2 (f16 acc) + GEMM3 (3-chain, epilogue col-scale)
    {
        dim3 grid(HD / 128, LA / 128, 2 * NB);
        gemm23_kernel<<<grid, 256, SMEM_G23>>>(P, QH, QL, hyH, pmH, pmL, scQ, AP, AHo);
    }
}